// round 1
// baseline (speedup 1.0000x reference)
#include <cuda_runtime.h>
#include <cuda_bf16.h>
#include <math.h>

// ---------------- problem constants ----------------
#define HH    320
#define WW    320
#define DIM   256
#define WIN   10
#define NH    8
#define HD    32
#define NTOK  (HH*WW)            // 102400
#define NWIN  (32*32)            // 1024 windows
#define NN    (WIN*WIN)          // 100 tokens / window
#define MROWS NTOK               // GEMM M
#define HID   1024
#define SCALE 0.17677669529663687f   // 32^-0.5
#define LNEPS 1e-5f

// ---------------- scratch (static device, no allocations) ----------------
__device__ float g_win[MROWS*DIM];   // LN1 output, window-partitioned order
__device__ float g_q  [MROWS*DIM];   // Q (scaled)
__device__ float g_kv [MROWS*2*DIM]; // K | V
__device__ float g_o  [MROWS*DIM];   // attention out (window order)
__device__ float g_x2 [MROWS*DIM];   // x + attn branch (token order)
__device__ float g_h2 [MROWS*DIM];   // LN2 output
__device__ float g_f  [MROWS*HID];   // gelu(h2@l1+b)  (token order, NHWC)
__device__ float g_f2 [MROWS*HID];   // gelu(dwconv(f)+b)

__device__ __forceinline__ float gelu_exact(float v) {
    return 0.5f * v * (1.0f + erff(v * 0.70710678118654752f));
}

// ---------------- LayerNorm kernels (1 block per token, 256 threads) ----------------
__device__ __forceinline__ void ln_core(float v, const float* __restrict__ g,
                                        const float* __restrict__ b, int tid, float& y) {
    float s = v, ss = v * v;
    #pragma unroll
    for (int o = 16; o; o >>= 1) {
        s  += __shfl_xor_sync(0xffffffffu, s,  o);
        ss += __shfl_xor_sync(0xffffffffu, ss, o);
    }
    __shared__ float sh[8], sh2[8];
    int warp = tid >> 5, lane = tid & 31;
    if (lane == 0) { sh[warp] = s; sh2[warp] = ss; }
    __syncthreads();
    float ts = 0.f, tss = 0.f;
    #pragma unroll
    for (int i = 0; i < 8; i++) { ts += sh[i]; tss += sh2[i]; }
    float mean = ts * (1.0f / DIM);
    float var  = tss * (1.0f / DIM) - mean * mean;
    y = (v - mean) * rsqrtf(var + LNEPS) * g[tid] + b[tid];
}

// LN1: x (token order) -> g_win (window-partitioned order)
__global__ void ln1_kernel(const float* __restrict__ x,
                           const float* __restrict__ g, const float* __restrict__ b) {
    int t = blockIdx.x, tid = threadIdx.x;
    float v = x[(size_t)t * DIM + tid];
    float y; ln_core(v, g, b, tid, y);
    int h = t / WW, w = t - h * WW;
    int r = ((h / WIN) * 32 + (w / WIN)) * NN + (h % WIN) * WIN + (w % WIN);
    g_win[(size_t)r * DIM + tid] = y;
}

// LN2: g_x2 -> g_h2 (token order)
__global__ void ln2_kernel(const float* __restrict__ g, const float* __restrict__ b) {
    int t = blockIdx.x, tid = threadIdx.x;
    float v = g_x2[(size_t)t * DIM + tid];
    float y; ln_core(v, g, b, tid, y);
    g_h2[(size_t)t * DIM + tid] = y;
}

// ---------------- SGEMM 128x128x8, 256 threads, 8x8 per thread ----------------
// MODE 0: g_win @ Bw -> g_q ,  C = (acc+bias)*SCALE
// MODE 1: g_win @ Bw -> g_kv,  C = acc+bias
// MODE 2: g_o   @ Bw -> g_x2,  window-reverse row->token, C[tok] = res[tok] + acc + bias
// MODE 3: g_h2  @ Bw -> g_f ,  C = gelu(acc+bias)
// MODE 4: g_f2  @ Bw -> Cout,  C = g_x2 + acc + bias   (final output)
template<int MODE>
__launch_bounds__(256)
__global__ void sgemm(const float* __restrict__ Bw, const float* __restrict__ bias,
                      const float* __restrict__ res, float* __restrict__ Cout,
                      int Ndim, int Kdim) {
    const float* A; float* C;
    if constexpr (MODE == 0) { A = g_win; C = g_q;  }
    else if constexpr (MODE == 1) { A = g_win; C = g_kv; }
    else if constexpr (MODE == 2) { A = g_o;   C = g_x2; }
    else if constexpr (MODE == 3) { A = g_h2;  C = g_f;  }
    else                          { A = g_f2;  C = Cout; }

    constexpr int BM = 128, BN = 128, BK = 8;
    __shared__ float As[BK][BM];
    __shared__ float Bs[BK][BN + 4];

    int tid = threadIdx.x;
    int bx = blockIdx.x, by = blockIdx.y;
    int aRow = tid >> 1;            // 0..127
    int aCol = (tid & 1) << 2;      // 0 or 4
    int bRow = tid >> 5;            // 0..7
    int bCol = (tid & 31) << 2;     // 0..124
    int tx = tid & 15, ty = tid >> 4;

    const float* Ap = A  + (size_t)(by * BM + aRow) * Kdim + aCol;
    const float* Bp = Bw + (size_t)bRow * Ndim + bx * BN + bCol;

    float acc[8][8];
    #pragma unroll
    for (int i = 0; i < 8; i++)
        #pragma unroll
        for (int j = 0; j < 8; j++) acc[i][j] = 0.f;

    for (int k0 = 0; k0 < Kdim; k0 += BK) {
        float4 av = *(const float4*)Ap;
        float4 bv = *(const float4*)Bp;
        As[aCol + 0][aRow] = av.x;
        As[aCol + 1][aRow] = av.y;
        As[aCol + 2][aRow] = av.z;
        As[aCol + 3][aRow] = av.w;
        *(float4*)&Bs[bRow][bCol] = bv;
        __syncthreads();
        #pragma unroll
        for (int k = 0; k < BK; k++) {
            float ar[8], br[8];
            *(float4*)(ar)     = *(const float4*)&As[k][ty * 8];
            *(float4*)(ar + 4) = *(const float4*)&As[k][ty * 8 + 4];
            *(float4*)(br)     = *(const float4*)&Bs[k][tx * 8];
            *(float4*)(br + 4) = *(const float4*)&Bs[k][tx * 8 + 4];
            #pragma unroll
            for (int i = 0; i < 8; i++)
                #pragma unroll
                for (int j = 0; j < 8; j++)
                    acc[i][j] = fmaf(ar[i], br[j], acc[i][j]);
        }
        __syncthreads();
        Ap += BK;
        Bp += (size_t)BK * Ndim;
    }

    int rowBase = by * 128 + ty * 8;
    int colBase = bx * 128 + tx * 8;
    #pragma unroll
    for (int i = 0; i < 8; i++) {
        int r = rowBase + i;
        #pragma unroll
        for (int j = 0; j < 8; j++) {
            int c = colBase + j;
            float v = acc[i][j] + bias[c];
            if constexpr (MODE == 0) {
                C[(size_t)r * Ndim + c] = v * SCALE;
            } else if constexpr (MODE == 1) {
                C[(size_t)r * Ndim + c] = v;
            } else if constexpr (MODE == 2) {
                int wwin = r / NN, p = r - wwin * NN;
                int tok = ((wwin >> 5) * WIN + p / WIN) * WW + (wwin & 31) * WIN + (p % WIN);
                C[(size_t)tok * DIM + c] = res[(size_t)tok * DIM + c] + v;
            } else if constexpr (MODE == 3) {
                C[(size_t)r * Ndim + c] = gelu_exact(v);
            } else {
                C[(size_t)r * Ndim + c] = g_x2[(size_t)r * DIM + c] + v;
            }
        }
    }
}

// ---------------- Windowed attention: 1 block per (window, head), 256 threads ----------------
__global__ __launch_bounds__(256)
void attn_kernel(const float* __restrict__ rpb) {
    __shared__ float qs[NN][HD + 1];
    __shared__ float ks[NN][HD + 1];
    __shared__ float vs[NN][HD + 1];
    __shared__ float rs[361];           // rpb column for this head
    __shared__ float ps[8][NN + 4];     // one softmax row per warp

    int blk  = blockIdx.x;
    int w    = blk >> 3;        // window
    int head = blk & 7;
    int tid  = threadIdx.x;
    int warp = tid >> 5, lane = tid & 31;

    for (int i = tid; i < 361; i += 256) rs[i] = rpb[i * NH + head];
    for (int i = tid; i < NN * HD; i += 256) {
        int n = i >> 5, d = i & 31;
        size_t base = (size_t)(w * NN + n);
        qs[n][d] = g_q [base * DIM + head * HD + d];
        ks[n][d] = g_kv[base * (2 * DIM) + head * HD + d];
        vs[n][d] = g_kv[base * (2 * DIM) + DIM + head * HD + d];
    }
    __syncthreads();

    for (int n = warp; n < NN; n += 8) {
        int ni = n / WIN, nj = n - ni * WIN;
        float e[4];
        float mx = -1e30f;
        #pragma unroll
        for (int jj = 0; jj < 4; jj++) {
            int m = lane + jj * 32;
            float s = -1e30f;
            if (m < NN) {
                float a = 0.f;
                #pragma unroll
                for (int d = 0; d < HD; d++) a = fmaf(qs[n][d], ks[m][d], a);
                int mi = m / WIN, mj = m - mi * WIN;
                s = a + rs[(ni - mi + WIN - 1) * (2 * WIN - 1) + (nj - mj + WIN - 1)];
            }
            e[jj] = s;
            mx = fmaxf(mx, s);
        }
        #pragma unroll
        for (int o = 16; o; o >>= 1) mx = fmaxf(mx, __shfl_xor_sync(0xffffffffu, mx, o));
        float sum = 0.f;
        #pragma unroll
        for (int jj = 0; jj < 4; jj++) {
            int m = lane + jj * 32;
            float p = (m < NN) ? expf(e[jj] - mx) : 0.f;
            e[jj] = p;
            sum += p;
        }
        #pragma unroll
        for (int o = 16; o; o >>= 1) sum += __shfl_xor_sync(0xffffffffu, sum, o);
        float inv = 1.0f / sum;
        #pragma unroll
        for (int jj = 0; jj < 4; jj++) {
            int m = lane + jj * 32;
            if (m < NN) ps[warp][m] = e[jj] * inv;
        }
        __syncwarp();
        float a = 0.f;
        #pragma unroll 4
        for (int m = 0; m < NN; m++) a = fmaf(ps[warp][m], vs[m][lane], a);
        g_o[(size_t)(w * NN + n) * DIM + head * HD + lane] = a;
        __syncwarp();
    }
}

// ---------------- Depthwise 3x3 conv (NHWC, C=1024) + bias + gelu ----------------
__global__ __launch_bounds__(256)
void dwconv_kernel(const float* __restrict__ dw_w, const float* __restrict__ dw_b) {
    int c = blockIdx.x * 256 + threadIdx.x;  // 0..1023
    int w = blockIdx.y;
    int h = blockIdx.z;
    float wk[9];
    #pragma unroll
    for (int t = 0; t < 9; t++) wk[t] = dw_w[c * 9 + t];
    float acc = dw_b[c];
    #pragma unroll
    for (int dh = -1; dh <= 1; dh++) {
        int hh = h + dh;
        if ((unsigned)hh >= HH) continue;
        #pragma unroll
        for (int dw2 = -1; dw2 <= 1; dw2++) {
            int ww2 = w + dw2;
            if ((unsigned)ww2 >= WW) continue;
            acc = fmaf(g_f[((size_t)hh * WW + ww2) * HID + c], wk[(dh + 1) * 3 + (dw2 + 1)], acc);
        }
    }
    g_f2[((size_t)h * WW + w) * HID + c] = gelu_exact(acc);
}

// ---------------- launch ----------------
extern "C" void kernel_launch(void* const* d_in, const int* in_sizes, int n_in,
                              void* d_out, int out_size) {
    const float* x       = (const float*)d_in[0];
    const float* norm1_g = (const float*)d_in[1];
    const float* norm1_b = (const float*)d_in[2];
    const float* wq      = (const float*)d_in[3];
    const float* bq      = (const float*)d_in[4];
    const float* wkv     = (const float*)d_in[5];
    const float* bkv     = (const float*)d_in[6];
    const float* rpb     = (const float*)d_in[7];
    const float* proj_w  = (const float*)d_in[8];
    const float* proj_b  = (const float*)d_in[9];
    const float* norm2_g = (const float*)d_in[10];
    const float* norm2_b = (const float*)d_in[11];
    const float* l1_w    = (const float*)d_in[12];
    const float* l1_b    = (const float*)d_in[13];
    const float* dw_w    = (const float*)d_in[14];
    const float* dw_b    = (const float*)d_in[15];
    const float* l2_w    = (const float*)d_in[16];
    const float* l2_b    = (const float*)d_in[17];
    float* out = (float*)d_out;

    ln1_kernel<<<NTOK, 256>>>(x, norm1_g, norm1_b);
    sgemm<0><<<dim3(DIM / 128,    MROWS / 128), 256>>>(wq,     bq,     nullptr, nullptr, DIM,     DIM);
    sgemm<1><<<dim3(2 * DIM / 128, MROWS / 128), 256>>>(wkv,    bkv,    nullptr, nullptr, 2 * DIM, DIM);
    attn_kernel<<<NWIN * NH, 256>>>(rpb);
    sgemm<2><<<dim3(DIM / 128,    MROWS / 128), 256>>>(proj_w, proj_b, x,       nullptr, DIM,     DIM);
    ln2_kernel<<<NTOK, 256>>>(norm2_g, norm2_b);
    sgemm<3><<<dim3(HID / 128,    MROWS / 128), 256>>>(l1_w,   l1_b,   nullptr, nullptr, HID,     DIM);
    dwconv_kernel<<<dim3(HID / 256, WW, HH), 256>>>(dw_w, dw_b);
    sgemm<4><<<dim3(DIM / 128,    MROWS / 128), 256>>>(l2_w,   l2_b,   nullptr, out,     DIM,     HID);
}

// round 2
// speedup vs baseline: 1.7588x; 1.7588x over previous
#include <cuda_runtime.h>
#include <cuda_bf16.h>
#include <math.h>

// ---------------- problem constants ----------------
#define HH    320
#define WW    320
#define DIM   256
#define WIN   10
#define NH    8
#define HD    32
#define NTOK  (HH*WW)            // 102400
#define NWIN  (32*32)            // 1024 windows
#define NN    (WIN*WIN)          // 100 tokens / window
#define MROWS NTOK               // GEMM M
#define HID   1024
#define SCALE 0.17677669529663687f   // 32^-0.5
#define LNEPS 1e-5f

// ---------------- scratch (static device, no allocations) ----------------
__device__ float g_win[MROWS*DIM];   // LN1 output, window-partitioned order
__device__ float g_q  [MROWS*DIM];   // Q (scaled)
__device__ float g_kv [MROWS*2*DIM]; // K | V
__device__ float g_o  [MROWS*DIM];   // attention out (window order)
__device__ float g_x2 [MROWS*DIM];   // x + attn branch (token order)
__device__ float g_h2 [MROWS*DIM];   // LN2 output
__device__ float g_f  [MROWS*HID];   // gelu(h2@l1+b)  (token order, NHWC)
__device__ float g_f2 [MROWS*HID];   // gelu(dwconv(f)+b)

__device__ __forceinline__ float gelu_exact(float v) {
    return 0.5f * v * (1.0f + erff(v * 0.70710678118654752f));
}

__device__ __forceinline__ unsigned tf32u(float x) {
    unsigned r;
    asm("cvt.rna.tf32.f32 %0, %1;" : "=r"(r) : "f"(x));
    return r;
}

__device__ __forceinline__ void mma_tf32(float c[4], unsigned a0, unsigned a1,
                                         unsigned a2, unsigned a3,
                                         unsigned b0, unsigned b1) {
    asm volatile("mma.sync.aligned.m16n8k8.row.col.f32.tf32.tf32.f32 "
                 "{%0,%1,%2,%3}, {%4,%5,%6,%7}, {%8,%9}, {%0,%1,%2,%3};"
                 : "+f"(c[0]), "+f"(c[1]), "+f"(c[2]), "+f"(c[3])
                 : "r"(a0), "r"(a1), "r"(a2), "r"(a3), "r"(b0), "r"(b1));
}

// ---------------- LayerNorm kernels (1 block per token, 256 threads) ----------------
__device__ __forceinline__ void ln_core(float v, const float* __restrict__ g,
                                        const float* __restrict__ b, int tid, float& y) {
    float s = v, ss = v * v;
    #pragma unroll
    for (int o = 16; o; o >>= 1) {
        s  += __shfl_xor_sync(0xffffffffu, s,  o);
        ss += __shfl_xor_sync(0xffffffffu, ss, o);
    }
    __shared__ float sh[8], sh2[8];
    int warp = tid >> 5, lane = tid & 31;
    if (lane == 0) { sh[warp] = s; sh2[warp] = ss; }
    __syncthreads();
    float ts = 0.f, tss = 0.f;
    #pragma unroll
    for (int i = 0; i < 8; i++) { ts += sh[i]; tss += sh2[i]; }
    float mean = ts * (1.0f / DIM);
    float var  = tss * (1.0f / DIM) - mean * mean;
    y = (v - mean) * rsqrtf(var + LNEPS) * g[tid] + b[tid];
}

// LN1: x (token order) -> g_win (window-partitioned order)
__global__ void ln1_kernel(const float* __restrict__ x,
                           const float* __restrict__ g, const float* __restrict__ b) {
    int t = blockIdx.x, tid = threadIdx.x;
    float v = x[(size_t)t * DIM + tid];
    float y; ln_core(v, g, b, tid, y);
    int h = t / WW, w = t - h * WW;
    int r = ((h / WIN) * 32 + (w / WIN)) * NN + (h % WIN) * WIN + (w % WIN);
    g_win[(size_t)r * DIM + tid] = y;
}

// LN2: g_x2 -> g_h2 (token order)
__global__ void ln2_kernel(const float* __restrict__ g, const float* __restrict__ b) {
    int t = blockIdx.x, tid = threadIdx.x;
    float v = g_x2[(size_t)t * DIM + tid];
    float y; ln_core(v, g, b, tid, y);
    g_h2[(size_t)t * DIM + tid] = y;
}

// ---------------- TF32 tensor-core GEMM 128x128x16, 256 threads ----------------
// warp layout 2(M) x 4(N); warp tile 64x32 = 4x4 m16n8k8 tiles.
// MODE 0: g_win @ Bw -> g_q ,  C = (acc+bias)*SCALE
// MODE 1: g_win @ Bw -> g_kv,  C = acc+bias
// MODE 2: g_o   @ Bw -> g_x2,  window-reverse row->token, C[tok] = res[tok] + acc + bias
// MODE 3: g_h2  @ Bw -> g_f ,  C = gelu(acc+bias)
// MODE 4: g_f2  @ Bw -> Cout,  C = g_x2 + acc + bias   (final output)
template<int MODE>
__launch_bounds__(256, 2)
__global__ void tgemm(const float* __restrict__ Bw, const float* __restrict__ bias,
                      const float* __restrict__ res, float* __restrict__ Cout,
                      int Ndim, int Kdim) {
    const float* A; float* C;
    if constexpr (MODE == 0) { A = g_win; C = g_q;  }
    else if constexpr (MODE == 1) { A = g_win; C = g_kv; }
    else if constexpr (MODE == 2) { A = g_o;   C = g_x2; }
    else if constexpr (MODE == 3) { A = g_h2;  C = g_f;  }
    else                          { A = g_f2;  C = Cout; }

    constexpr int BM = 128, BN = 128, BK = 16;
    __shared__ unsigned As[2][BK][BM + 8];   // [k][m], conflict-free frag reads
    __shared__ unsigned Bs[2][BK][BN + 8];   // [k][n]

    const int tid  = threadIdx.x;
    const int bx   = blockIdx.x, by = blockIdx.y;
    const int lane = tid & 31;
    const int warp = tid >> 5;
    const int warpM = warp & 1;      // 0..1
    const int warpN = warp >> 1;     // 0..3
    const int gid = lane >> 2;       // 0..7
    const int tig = lane & 3;        // 0..3

    // global load mapping
    const int aRow0 = tid >> 2;          // 0..63  (also +64)
    const int aCol  = (tid & 3) << 2;    // 0,4,8,12
    const int bRow0 = tid >> 5;          // 0..7   (also +8)
    const int bCol  = lane << 2;         // 0..124

    const float* Aptr = A  + (size_t)(by * BM + aRow0) * Kdim + aCol;
    const float* Bptr = Bw + (size_t)bRow0 * Ndim + bx * BN + bCol;

    float acc[4][4][4];
    #pragma unroll
    for (int i = 0; i < 4; i++)
        #pragma unroll
        for (int j = 0; j < 4; j++)
            #pragma unroll
            for (int r = 0; r < 4; r++) acc[i][j][r] = 0.f;

    const int tiles = Kdim / BK;

    // prologue: load tile 0
    float4 a0v = *(const float4*)(Aptr);
    float4 a1v = *(const float4*)(Aptr + (size_t)64 * Kdim);
    float4 b0v = *(const float4*)(Bptr);
    float4 b1v = *(const float4*)(Bptr + (size_t)8 * Ndim);

    int buf = 0;
    // sts tile 0
    {
        As[buf][aCol + 0][aRow0]      = tf32u(a0v.x);
        As[buf][aCol + 1][aRow0]      = tf32u(a0v.y);
        As[buf][aCol + 2][aRow0]      = tf32u(a0v.z);
        As[buf][aCol + 3][aRow0]      = tf32u(a0v.w);
        As[buf][aCol + 0][aRow0 + 64] = tf32u(a1v.x);
        As[buf][aCol + 1][aRow0 + 64] = tf32u(a1v.y);
        As[buf][aCol + 2][aRow0 + 64] = tf32u(a1v.z);
        As[buf][aCol + 3][aRow0 + 64] = tf32u(a1v.w);
        *(uint4*)&Bs[buf][bRow0][bCol]     = make_uint4(tf32u(b0v.x), tf32u(b0v.y), tf32u(b0v.z), tf32u(b0v.w));
        *(uint4*)&Bs[buf][bRow0 + 8][bCol] = make_uint4(tf32u(b1v.x), tf32u(b1v.y), tf32u(b1v.z), tf32u(b1v.w));
    }
    __syncthreads();

    for (int t = 0; t < tiles; t++) {
        if (t + 1 < tiles) {
            const float* Ap = Aptr + (size_t)(t + 1) * BK;
            const float* Bp = Bptr + (size_t)(t + 1) * BK * Ndim;
            a0v = *(const float4*)(Ap);
            a1v = *(const float4*)(Ap + (size_t)64 * Kdim);
            b0v = *(const float4*)(Bp);
            b1v = *(const float4*)(Bp + (size_t)8 * Ndim);
        }

        #pragma unroll
        for (int s = 0; s < 2; s++) {
            const int k0 = s * 8;
            unsigned af[4][4], bf[4][2];
            #pragma unroll
            for (int i = 0; i < 4; i++) {
                int m0 = warpM * 64 + i * 16;
                af[i][0] = As[buf][k0 + tig    ][m0 + gid];
                af[i][1] = As[buf][k0 + tig    ][m0 + gid + 8];
                af[i][2] = As[buf][k0 + tig + 4][m0 + gid];
                af[i][3] = As[buf][k0 + tig + 4][m0 + gid + 8];
            }
            #pragma unroll
            for (int j = 0; j < 4; j++) {
                int n0 = warpN * 32 + j * 8;
                bf[j][0] = Bs[buf][k0 + tig    ][n0 + gid];
                bf[j][1] = Bs[buf][k0 + tig + 4][n0 + gid];
            }
            #pragma unroll
            for (int i = 0; i < 4; i++)
                #pragma unroll
                for (int j = 0; j < 4; j++)
                    mma_tf32(acc[i][j], af[i][0], af[i][1], af[i][2], af[i][3],
                             bf[j][0], bf[j][1]);
        }

        if (t + 1 < tiles) {
            int nb = buf ^ 1;
            As[nb][aCol + 0][aRow0]      = tf32u(a0v.x);
            As[nb][aCol + 1][aRow0]      = tf32u(a0v.y);
            As[nb][aCol + 2][aRow0]      = tf32u(a0v.z);
            As[nb][aCol + 3][aRow0]      = tf32u(a0v.w);
            As[nb][aCol + 0][aRow0 + 64] = tf32u(a1v.x);
            As[nb][aCol + 1][aRow0 + 64] = tf32u(a1v.y);
            As[nb][aCol + 2][aRow0 + 64] = tf32u(a1v.z);
            As[nb][aCol + 3][aRow0 + 64] = tf32u(a1v.w);
            *(uint4*)&Bs[nb][bRow0][bCol]     = make_uint4(tf32u(b0v.x), tf32u(b0v.y), tf32u(b0v.z), tf32u(b0v.w));
            *(uint4*)&Bs[nb][bRow0 + 8][bCol] = make_uint4(tf32u(b1v.x), tf32u(b1v.y), tf32u(b1v.z), tf32u(b1v.w));
            __syncthreads();
            buf = nb;
        }
    }

    // ---------------- epilogue ----------------
    const int rowBase = by * BM + warpM * 64;
    const int colBase = bx * BN + warpN * 32;
    #pragma unroll
    for (int i = 0; i < 4; i++) {
        #pragma unroll
        for (int j = 0; j < 4; j++) {
            #pragma unroll
            for (int half = 0; half < 2; half++) {
                int r = rowBase + i * 16 + gid + half * 8;
                int c = colBase + j * 8 + tig * 2;
                float v0 = acc[i][j][half * 2 + 0] + bias[c];
                float v1 = acc[i][j][half * 2 + 1] + bias[c + 1];
                if constexpr (MODE == 0) {
                    C[(size_t)r * Ndim + c]     = v0 * SCALE;
                    C[(size_t)r * Ndim + c + 1] = v1 * SCALE;
                } else if constexpr (MODE == 1) {
                    C[(size_t)r * Ndim + c]     = v0;
                    C[(size_t)r * Ndim + c + 1] = v1;
                } else if constexpr (MODE == 2) {
                    int wwin = r / NN, p = r - wwin * NN;
                    int tok = ((wwin >> 5) * WIN + p / WIN) * WW + (wwin & 31) * WIN + (p % WIN);
                    C[(size_t)tok * DIM + c]     = res[(size_t)tok * DIM + c]     + v0;
                    C[(size_t)tok * DIM + c + 1] = res[(size_t)tok * DIM + c + 1] + v1;
                } else if constexpr (MODE == 3) {
                    C[(size_t)r * Ndim + c]     = gelu_exact(v0);
                    C[(size_t)r * Ndim + c + 1] = gelu_exact(v1);
                } else {
                    C[(size_t)r * Ndim + c]     = g_x2[(size_t)r * DIM + c]     + v0;
                    C[(size_t)r * Ndim + c + 1] = g_x2[(size_t)r * DIM + c + 1] + v1;
                }
            }
        }
    }
}

// ---------------- Windowed attention: 1 block per (window, head), 256 threads ----------------
__global__ __launch_bounds__(256)
void attn_kernel(const float* __restrict__ rpb) {
    __shared__ float qs[NN][HD + 1];
    __shared__ float ks[NN][HD + 1];
    __shared__ float vs[NN][HD + 1];
    __shared__ float rs[361];           // rpb column for this head
    __shared__ float ps[8][NN + 4];     // one softmax row per warp

    int blk  = blockIdx.x;
    int w    = blk >> 3;        // window
    int head = blk & 7;
    int tid  = threadIdx.x;
    int warp = tid >> 5, lane = tid & 31;

    for (int i = tid; i < 361; i += 256) rs[i] = rpb[i * NH + head];
    for (int i = tid; i < NN * HD; i += 256) {
        int n = i >> 5, d = i & 31;
        size_t base = (size_t)(w * NN + n);
        qs[n][d] = g_q [base * DIM + head * HD + d];
        ks[n][d] = g_kv[base * (2 * DIM) + head * HD + d];
        vs[n][d] = g_kv[base * (2 * DIM) + DIM + head * HD + d];
    }
    __syncthreads();

    for (int n = warp; n < NN; n += 8) {
        int ni = n / WIN, nj = n - ni * WIN;
        float e[4];
        float mx = -1e30f;
        #pragma unroll
        for (int jj = 0; jj < 4; jj++) {
            int m = lane + jj * 32;
            float s = -1e30f;
            if (m < NN) {
                float a = 0.f;
                #pragma unroll
                for (int d = 0; d < HD; d++) a = fmaf(qs[n][d], ks[m][d], a);
                int mi = m / WIN, mj = m - mi * WIN;
                s = a + rs[(ni - mi + WIN - 1) * (2 * WIN - 1) + (nj - mj + WIN - 1)];
            }
            e[jj] = s;
            mx = fmaxf(mx, s);
        }
        #pragma unroll
        for (int o = 16; o; o >>= 1) mx = fmaxf(mx, __shfl_xor_sync(0xffffffffu, mx, o));
        float sum = 0.f;
        #pragma unroll
        for (int jj = 0; jj < 4; jj++) {
            int m = lane + jj * 32;
            float p = (m < NN) ? expf(e[jj] - mx) : 0.f;
            e[jj] = p;
            sum += p;
        }
        #pragma unroll
        for (int o = 16; o; o >>= 1) sum += __shfl_xor_sync(0xffffffffu, sum, o);
        float inv = 1.0f / sum;
        #pragma unroll
        for (int jj = 0; jj < 4; jj++) {
            int m = lane + jj * 32;
            if (m < NN) ps[warp][m] = e[jj] * inv;
        }
        __syncwarp();
        float a = 0.f;
        #pragma unroll 4
        for (int m = 0; m < NN; m++) a = fmaf(ps[warp][m], vs[m][lane], a);
        g_o[(size_t)(w * NN + n) * DIM + head * HD + lane] = a;
        __syncwarp();
    }
}

// ---------------- Depthwise 3x3 conv (NHWC, C=1024) + bias + gelu ----------------
__global__ __launch_bounds__(256)
void dwconv_kernel(const float* __restrict__ dw_w, const float* __restrict__ dw_b) {
    int c = blockIdx.x * 256 + threadIdx.x;  // 0..1023
    int w = blockIdx.y;
    int h = blockIdx.z;
    float wk[9];
    #pragma unroll
    for (int t = 0; t < 9; t++) wk[t] = dw_w[c * 9 + t];
    float acc = dw_b[c];
    #pragma unroll
    for (int dh = -1; dh <= 1; dh++) {
        int hh = h + dh;
        if ((unsigned)hh >= HH) continue;
        #pragma unroll
        for (int dw2 = -1; dw2 <= 1; dw2++) {
            int ww2 = w + dw2;
            if ((unsigned)ww2 >= WW) continue;
            acc = fmaf(g_f[((size_t)hh * WW + ww2) * HID + c], wk[(dh + 1) * 3 + (dw2 + 1)], acc);
        }
    }
    g_f2[((size_t)h * WW + w) * HID + c] = gelu_exact(acc);
}

// ---------------- launch ----------------
extern "C" void kernel_launch(void* const* d_in, const int* in_sizes, int n_in,
                              void* d_out, int out_size) {
    const float* x       = (const float*)d_in[0];
    const float* norm1_g = (const float*)d_in[1];
    const float* norm1_b = (const float*)d_in[2];
    const float* wq      = (const float*)d_in[3];
    const float* bq      = (const float*)d_in[4];
    const float* wkv     = (const float*)d_in[5];
    const float* bkv     = (const float*)d_in[6];
    const float* rpb     = (const float*)d_in[7];
    const float* proj_w  = (const float*)d_in[8];
    const float* proj_b  = (const float*)d_in[9];
    const float* norm2_g = (const float*)d_in[10];
    const float* norm2_b = (const float*)d_in[11];
    const float* l1_w    = (const float*)d_in[12];
    const float* l1_b    = (const float*)d_in[13];
    const float* dw_w    = (const float*)d_in[14];
    const float* dw_b    = (const float*)d_in[15];
    const float* l2_w    = (const float*)d_in[16];
    const float* l2_b    = (const float*)d_in[17];
    float* out = (float*)d_out;

    ln1_kernel<<<NTOK, 256>>>(x, norm1_g, norm1_b);
    tgemm<0><<<dim3(DIM / 128,     MROWS / 128), 256>>>(wq,     bq,     nullptr, nullptr, DIM,     DIM);
    tgemm<1><<<dim3(2 * DIM / 128, MROWS / 128), 256>>>(wkv,    bkv,    nullptr, nullptr, 2 * DIM, DIM);
    attn_kernel<<<NWIN * NH, 256>>>(rpb);
    tgemm<2><<<dim3(DIM / 128,     MROWS / 128), 256>>>(proj_w, proj_b, x,       nullptr, DIM,     DIM);
    ln2_kernel<<<NTOK, 256>>>(norm2_g, norm2_b);
    tgemm<3><<<dim3(HID / 128,     MROWS / 128), 256>>>(l1_w,   l1_b,   nullptr, nullptr, HID,     DIM);
    dwconv_kernel<<<dim3(HID / 256, WW, HH), 256>>>(dw_w, dw_b);
    tgemm<4><<<dim3(DIM / 128,     MROWS / 128), 256>>>(l2_w,   l2_b,   nullptr, out,     DIM,     HID);
}

// round 3
// speedup vs baseline: 2.0389x; 1.1592x over previous
#include <cuda_runtime.h>
#include <cuda_bf16.h>
#include <math.h>

// ---------------- problem constants ----------------
#define HH    320
#define WW    320
#define DIM   256
#define WIN   10
#define NH    8
#define HD    32
#define NTOK  (HH*WW)            // 102400
#define NWIN  (32*32)            // 1024 windows
#define NN    (WIN*WIN)          // 100 tokens / window
#define MROWS NTOK               // GEMM M
#define HID   1024
#define SCALE 0.17677669529663687f   // 32^-0.5
#define LNEPS 1e-5f

typedef __nv_bfloat16 bf16;

// ---------------- scratch (static device, no allocations) ----------------
__device__ bf16  g_win[MROWS*DIM];    // LN1 output (bf16, window order)
__device__ float g_q  [MROWS*DIM];    // Q (scaled, fp32 for attention)
__device__ float g_kv [MROWS*2*DIM];  // K | V (fp32 for attention)
__device__ bf16  g_o  [MROWS*DIM];    // attention out (bf16, window order)
__device__ float g_x2 [MROWS*DIM];    // x + attn branch (fp32, token order)
__device__ bf16  g_h2 [MROWS*DIM];    // LN2 output (bf16)
__device__ bf16  g_f  [MROWS*HID];    // gelu(h2@l1+b) (bf16, NHWC)
__device__ bf16  g_f2 [MROWS*HID];    // gelu(dwconv(f)+b) (bf16)

// packed weights: u32 word = bf16x2 of (W[2*k2, n], W[2*k2+1, n]); layout [K/2][N]
__device__ unsigned p_wq  [128*256];
__device__ unsigned p_wkv [128*512];
__device__ unsigned p_proj[128*256];
__device__ unsigned p_l1  [128*1024];
__device__ unsigned p_l2  [512*256];

__device__ __forceinline__ float gelu_exact(float v) {
    return 0.5f * v * (1.0f + erff(v * 0.70710678118654752f));
}

__device__ __forceinline__ unsigned packbf(float a, float b) {
    __nv_bfloat162 t = __floats2bfloat162_rn(a, b);  // lo=a, hi=b
    return *(unsigned*)&t;
}

__device__ __forceinline__ void mma_bf16(float c[4], unsigned a0, unsigned a1,
                                         unsigned a2, unsigned a3,
                                         unsigned b0, unsigned b1) {
    asm volatile("mma.sync.aligned.m16n8k16.row.col.f32.bf16.bf16.f32 "
                 "{%0,%1,%2,%3}, {%4,%5,%6,%7}, {%8,%9}, {%0,%1,%2,%3};"
                 : "+f"(c[0]), "+f"(c[1]), "+f"(c[2]), "+f"(c[3])
                 : "r"(a0), "r"(a1), "r"(a2), "r"(a3), "r"(b0), "r"(b1));
}

// ---------------- weight pack kernel: [K,N] f32 -> [K/2][N] bf16x2 ----------------
__global__ void pack_w(const float* __restrict__ W, unsigned* __restrict__ out,
                       int K2, int N) {
    int i = blockIdx.x * 256 + threadIdx.x;
    if (i >= K2 * N) return;
    int k2 = i / N, n = i - k2 * N;
    out[i] = packbf(W[(size_t)(2 * k2) * N + n], W[(size_t)(2 * k2 + 1) * N + n]);
}

// ---------------- LayerNorm (1 block per token, 256 threads) ----------------
__device__ __forceinline__ void ln_core(float v, const float* __restrict__ g,
                                        const float* __restrict__ b, int tid, float& y) {
    float s = v, ss = v * v;
    #pragma unroll
    for (int o = 16; o; o >>= 1) {
        s  += __shfl_xor_sync(0xffffffffu, s,  o);
        ss += __shfl_xor_sync(0xffffffffu, ss, o);
    }
    __shared__ float sh[8], sh2[8];
    int warp = tid >> 5, lane = tid & 31;
    if (lane == 0) { sh[warp] = s; sh2[warp] = ss; }
    __syncthreads();
    float ts = 0.f, tss = 0.f;
    #pragma unroll
    for (int i = 0; i < 8; i++) { ts += sh[i]; tss += sh2[i]; }
    float mean = ts * (1.0f / DIM);
    float var  = tss * (1.0f / DIM) - mean * mean;
    y = (v - mean) * rsqrtf(var + LNEPS) * g[tid] + b[tid];
}

__global__ void ln1_kernel(const float* __restrict__ x,
                           const float* __restrict__ g, const float* __restrict__ b) {
    int t = blockIdx.x, tid = threadIdx.x;
    float v = x[(size_t)t * DIM + tid];
    float y; ln_core(v, g, b, tid, y);
    int h = t / WW, w = t - h * WW;
    int r = ((h / WIN) * 32 + (w / WIN)) * NN + (h % WIN) * WIN + (w % WIN);
    g_win[(size_t)r * DIM + tid] = __float2bfloat16(y);
}

__global__ void ln2_kernel(const float* __restrict__ g, const float* __restrict__ b) {
    int t = blockIdx.x, tid = threadIdx.x;
    float v = g_x2[(size_t)t * DIM + tid];
    float y; ln_core(v, g, b, tid, y);
    g_h2[(size_t)t * DIM + tid] = __float2bfloat16(y);
}

// ---------------- bf16 tensor-core GEMM 128x128x32, 256 threads ----------------
// A: bf16 row-major [M,K]; B: packed [K/2][N] bf16x2 words.
// warp layout 2(M) x 4(N); warp tile 64x32 = 4x4 m16n8k16 tiles.
// MODE 0: g_win -> g_q (f32),  C = (acc+bias)*SCALE
// MODE 1: g_win -> g_kv (f32), C = acc+bias
// MODE 2: g_o   -> g_x2 (f32), window-reverse, C[tok] = res[tok]+acc+bias
// MODE 3: g_h2  -> g_f (bf16), C = gelu(acc+bias)
// MODE 4: g_f2  -> out (f32),  C = g_x2 + acc + bias
template<int MODE>
__launch_bounds__(256, 2)
__global__ void tgemm(const unsigned* __restrict__ Bpk, const float* __restrict__ bias,
                      const float* __restrict__ res, float* __restrict__ Coutf,
                      int Ndim, int Kdim) {
    const bf16* A; float* Cf = nullptr; bf16* Ch = nullptr;
    if constexpr (MODE == 0) { A = g_win; Cf = g_q;  }
    else if constexpr (MODE == 1) { A = g_win; Cf = g_kv; }
    else if constexpr (MODE == 2) { A = g_o;   Cf = g_x2; }
    else if constexpr (MODE == 3) { A = g_h2;  Ch = g_f;  }
    else                          { A = g_f2;  Cf = Coutf; }

    constexpr int BM = 128, BN = 128, BK2 = 16;   // BK2 = k-pairs per tile (K tile = 32)
    constexpr int PAD = 8;
    __shared__ unsigned As[2][BK2][BM + PAD];   // [k2][m]
    __shared__ unsigned Bs[2][BK2][BN + PAD];   // [k2][n]

    const int tid  = threadIdx.x;
    const int bx   = blockIdx.x, by = blockIdx.y;
    const int lane = tid & 31;
    const int warp = tid >> 5;
    const int warpM = warp & 1;
    const int warpN = warp >> 1;
    const int gid = lane >> 2;
    const int tig = lane & 3;

    // global load mapping
    const int aRow = tid >> 1;           // 0..127
    const int uq   = tid & 1;            // k2 half: 0..7 or 8..15
    const int bK2  = tid >> 4;           // 0..15
    const int bN   = (tid & 15) << 3;    // 0,8,...,120

    const bf16*     Aptr = A   + (size_t)(by * BM + aRow) * Kdim + uq * 16;
    const unsigned* Bptr = Bpk + (size_t)bK2 * Ndim + bx * BN + bN;

    float acc[4][4][4];
    #pragma unroll
    for (int i = 0; i < 4; i++)
        #pragma unroll
        for (int j = 0; j < 4; j++)
            #pragma unroll
            for (int r = 0; r < 4; r++) acc[i][j][r] = 0.f;

    const int tiles = Kdim / 32;

    uint4 aq0 = *(const uint4*)(Aptr);
    uint4 aq1 = *(const uint4*)(Aptr + 8);
    uint4 bq0 = *(const uint4*)(Bptr);
    uint4 bq1 = *(const uint4*)(Bptr + 4);

    int buf = 0;
    {
        int k2b = uq * 8;
        As[buf][k2b + 0][aRow] = aq0.x;
        As[buf][k2b + 1][aRow] = aq0.y;
        As[buf][k2b + 2][aRow] = aq0.z;
        As[buf][k2b + 3][aRow] = aq0.w;
        As[buf][k2b + 4][aRow] = aq1.x;
        As[buf][k2b + 5][aRow] = aq1.y;
        As[buf][k2b + 6][aRow] = aq1.z;
        As[buf][k2b + 7][aRow] = aq1.w;
        *(uint4*)&Bs[buf][bK2][bN]     = bq0;
        *(uint4*)&Bs[buf][bK2][bN + 4] = bq1;
    }
    __syncthreads();

    for (int t = 0; t < tiles; t++) {
        if (t + 1 < tiles) {
            const bf16*     Ap = Aptr + (size_t)(t + 1) * 32;
            const unsigned* Bp = Bptr + (size_t)(t + 1) * BK2 * Ndim;
            aq0 = *(const uint4*)(Ap);
            aq1 = *(const uint4*)(Ap + 8);
            bq0 = *(const uint4*)(Bp);
            bq1 = *(const uint4*)(Bp + 4);
        }

        #pragma unroll
        for (int s = 0; s < 2; s++) {
            const int k2o = s * 8;
            unsigned af[4][4], bfr[4][2];
            #pragma unroll
            for (int i = 0; i < 4; i++) {
                int m0 = warpM * 64 + i * 16;
                af[i][0] = As[buf][k2o + tig    ][m0 + gid];
                af[i][1] = As[buf][k2o + tig    ][m0 + gid + 8];
                af[i][2] = As[buf][k2o + tig + 4][m0 + gid];
                af[i][3] = As[buf][k2o + tig + 4][m0 + gid + 8];
            }
            #pragma unroll
            for (int j = 0; j < 4; j++) {
                int n0 = warpN * 32 + j * 8;
                bfr[j][0] = Bs[buf][k2o + tig    ][n0 + gid];
                bfr[j][1] = Bs[buf][k2o + tig + 4][n0 + gid];
            }
            #pragma unroll
            for (int i = 0; i < 4; i++)
                #pragma unroll
                for (int j = 0; j < 4; j++)
                    mma_bf16(acc[i][j], af[i][0], af[i][1], af[i][2], af[i][3],
                             bfr[j][0], bfr[j][1]);
        }

        if (t + 1 < tiles) {
            int nb = buf ^ 1;
            int k2b = uq * 8;
            As[nb][k2b + 0][aRow] = aq0.x;
            As[nb][k2b + 1][aRow] = aq0.y;
            As[nb][k2b + 2][aRow] = aq0.z;
            As[nb][k2b + 3][aRow] = aq0.w;
            As[nb][k2b + 4][aRow] = aq1.x;
            As[nb][k2b + 5][aRow] = aq1.y;
            As[nb][k2b + 6][aRow] = aq1.z;
            As[nb][k2b + 7][aRow] = aq1.w;
            *(uint4*)&Bs[nb][bK2][bN]     = bq0;
            *(uint4*)&Bs[nb][bK2][bN + 4] = bq1;
            __syncthreads();
            buf = nb;
        }
    }

    // ---------------- epilogue ----------------
    const int rowBase = by * BM + warpM * 64;
    const int colBase = bx * BN + warpN * 32;
    #pragma unroll
    for (int i = 0; i < 4; i++) {
        #pragma unroll
        for (int j = 0; j < 4; j++) {
            #pragma unroll
            for (int half = 0; half < 2; half++) {
                int r = rowBase + i * 16 + gid + half * 8;
                int c = colBase + j * 8 + tig * 2;
                float v0 = acc[i][j][half * 2 + 0] + bias[c];
                float v1 = acc[i][j][half * 2 + 1] + bias[c + 1];
                if constexpr (MODE == 0) {
                    Cf[(size_t)r * Ndim + c]     = v0 * SCALE;
                    Cf[(size_t)r * Ndim + c + 1] = v1 * SCALE;
                } else if constexpr (MODE == 1) {
                    Cf[(size_t)r * Ndim + c]     = v0;
                    Cf[(size_t)r * Ndim + c + 1] = v1;
                } else if constexpr (MODE == 2) {
                    int wwin = r / NN, p = r - wwin * NN;
                    int tok = ((wwin >> 5) * WIN + p / WIN) * WW + (wwin & 31) * WIN + (p % WIN);
                    Cf[(size_t)tok * DIM + c]     = res[(size_t)tok * DIM + c]     + v0;
                    Cf[(size_t)tok * DIM + c + 1] = res[(size_t)tok * DIM + c + 1] + v1;
                } else if constexpr (MODE == 3) {
                    Ch[(size_t)r * Ndim + c]     = __float2bfloat16(gelu_exact(v0));
                    Ch[(size_t)r * Ndim + c + 1] = __float2bfloat16(gelu_exact(v1));
                } else {
                    Cf[(size_t)r * Ndim + c]     = g_x2[(size_t)r * DIM + c]     + v0;
                    Cf[(size_t)r * Ndim + c + 1] = g_x2[(size_t)r * DIM + c + 1] + v1;
                }
            }
        }
    }
}

// ---------------- Windowed attention: 1 block per (window, head), 256 threads ----------------
__global__ __launch_bounds__(256)
void attn_kernel(const float* __restrict__ rpb) {
    __shared__ float qs[NN][HD + 1];
    __shared__ float ks[NN][HD + 1];
    __shared__ float vs[NN][HD + 1];
    __shared__ float rs[361];
    __shared__ float ps[8][NN + 4];

    int blk  = blockIdx.x;
    int w    = blk >> 3;
    int head = blk & 7;
    int tid  = threadIdx.x;
    int warp = tid >> 5, lane = tid & 31;

    for (int i = tid; i < 361; i += 256) rs[i] = rpb[i * NH + head];
    for (int i = tid; i < NN * HD; i += 256) {
        int n = i >> 5, d = i & 31;
        size_t base = (size_t)(w * NN + n);
        qs[n][d] = g_q [base * DIM + head * HD + d];
        ks[n][d] = g_kv[base * (2 * DIM) + head * HD + d];
        vs[n][d] = g_kv[base * (2 * DIM) + DIM + head * HD + d];
    }
    __syncthreads();

    for (int n = warp; n < NN; n += 8) {
        int ni = n / WIN, nj = n - ni * WIN;
        float e[4];
        float mx = -1e30f;
        #pragma unroll
        for (int jj = 0; jj < 4; jj++) {
            int m = lane + jj * 32;
            float s = -1e30f;
            if (m < NN) {
                float a = 0.f;
                #pragma unroll
                for (int d = 0; d < HD; d++) a = fmaf(qs[n][d], ks[m][d], a);
                int mi = m / WIN, mj = m - mi * WIN;
                s = a + rs[(ni - mi + WIN - 1) * (2 * WIN - 1) + (nj - mj + WIN - 1)];
            }
            e[jj] = s;
            mx = fmaxf(mx, s);
        }
        #pragma unroll
        for (int o = 16; o; o >>= 1) mx = fmaxf(mx, __shfl_xor_sync(0xffffffffu, mx, o));
        float sum = 0.f;
        #pragma unroll
        for (int jj = 0; jj < 4; jj++) {
            int m = lane + jj * 32;
            float p = (m < NN) ? expf(e[jj] - mx) : 0.f;
            e[jj] = p;
            sum += p;
        }
        #pragma unroll
        for (int o = 16; o; o >>= 1) sum += __shfl_xor_sync(0xffffffffu, sum, o);
        float inv = 1.0f / sum;
        #pragma unroll
        for (int jj = 0; jj < 4; jj++) {
            int m = lane + jj * 32;
            if (m < NN) ps[warp][m] = e[jj] * inv;
        }
        __syncwarp();
        float a = 0.f;
        #pragma unroll 4
        for (int m = 0; m < NN; m++) a = fmaf(ps[warp][m], vs[m][lane], a);
        g_o[(size_t)(w * NN + n) * DIM + head * HD + lane] = __float2bfloat16(a);
        __syncwarp();
    }
}

// ---------------- Depthwise 3x3 conv (NHWC, C=1024) + bias + gelu ----------------
__global__ __launch_bounds__(256)
void dwconv_kernel(const float* __restrict__ dw_w, const float* __restrict__ dw_b) {
    int c = blockIdx.x * 256 + threadIdx.x;
    int w = blockIdx.y;
    int h = blockIdx.z;
    float wk[9];
    #pragma unroll
    for (int t = 0; t < 9; t++) wk[t] = dw_w[c * 9 + t];
    float acc = dw_b[c];
    #pragma unroll
    for (int dh = -1; dh <= 1; dh++) {
        int hh = h + dh;
        if ((unsigned)hh >= HH) continue;
        #pragma unroll
        for (int dw2 = -1; dw2 <= 1; dw2++) {
            int ww2 = w + dw2;
            if ((unsigned)ww2 >= WW) continue;
            acc = fmaf(__bfloat162float(g_f[((size_t)hh * WW + ww2) * HID + c]),
                       wk[(dh + 1) * 3 + (dw2 + 1)], acc);
        }
    }
    g_f2[((size_t)h * WW + w) * HID + c] = __float2bfloat16(gelu_exact(acc));
}

// ---------------- launch ----------------
extern "C" void kernel_launch(void* const* d_in, const int* in_sizes, int n_in,
                              void* d_out, int out_size) {
    const float* x       = (const float*)d_in[0];
    const float* norm1_g = (const float*)d_in[1];
    const float* norm1_b = (const float*)d_in[2];
    const float* wq      = (const float*)d_in[3];
    const float* bq      = (const float*)d_in[4];
    const float* wkv     = (const float*)d_in[5];
    const float* bkv     = (const float*)d_in[6];
    const float* rpb     = (const float*)d_in[7];
    const float* proj_w  = (const float*)d_in[8];
    const float* proj_b  = (const float*)d_in[9];
    const float* norm2_g = (const float*)d_in[10];
    const float* norm2_b = (const float*)d_in[11];
    const float* l1_w    = (const float*)d_in[12];
    const float* l1_b    = (const float*)d_in[13];
    const float* dw_w    = (const float*)d_in[14];
    const float* dw_b    = (const float*)d_in[15];
    const float* l2_w    = (const float*)d_in[16];
    const float* l2_b    = (const float*)d_in[17];
    float* out = (float*)d_out;

    unsigned *pq, *pkv, *pproj, *pl1, *pl2;
    cudaGetSymbolAddress((void**)&pq,    p_wq);
    cudaGetSymbolAddress((void**)&pkv,   p_wkv);
    cudaGetSymbolAddress((void**)&pproj, p_proj);
    cudaGetSymbolAddress((void**)&pl1,   p_l1);
    cudaGetSymbolAddress((void**)&pl2,   p_l2);

    pack_w<<<(128*256  + 255)/256, 256>>>(wq,     pq,    128, 256);
    pack_w<<<(128*512  + 255)/256, 256>>>(wkv,    pkv,   128, 512);
    pack_w<<<(128*256  + 255)/256, 256>>>(proj_w, pproj, 128, 256);
    pack_w<<<(128*1024 + 255)/256, 256>>>(l1_w,   pl1,   128, 1024);
    pack_w<<<(512*256  + 255)/256, 256>>>(l2_w,   pl2,   512, 256);

    ln1_kernel<<<NTOK, 256>>>(x, norm1_g, norm1_b);
    tgemm<0><<<dim3(DIM / 128,     MROWS / 128), 256>>>(pq,    bq,     nullptr, nullptr, DIM,     DIM);
    tgemm<1><<<dim3(2 * DIM / 128, MROWS / 128), 256>>>(pkv,   bkv,    nullptr, nullptr, 2 * DIM, DIM);
    attn_kernel<<<NWIN * NH, 256>>>(rpb);
    tgemm<2><<<dim3(DIM / 128,     MROWS / 128), 256>>>(pproj, proj_b, x,       nullptr, DIM,     DIM);
    ln2_kernel<<<NTOK, 256>>>(norm2_g, norm2_b);
    tgemm<3><<<dim3(HID / 128,     MROWS / 128), 256>>>(pl1,   l1_b,   nullptr, nullptr, HID,     DIM);
    dwconv_kernel<<<dim3(HID / 256, WW, HH), 256>>>(dw_w, dw_b);
    tgemm<4><<<dim3(DIM / 128,     MROWS / 128), 256>>>(pl2,   l2_b,   nullptr, out,     DIM,     HID);
}

// round 4
// speedup vs baseline: 2.6649x; 1.3070x over previous
#include <cuda_runtime.h>
#include <cuda_bf16.h>
#include <math.h>

// ---------------- problem constants ----------------
#define HH    320
#define WW    320
#define DIM   256
#define WIN   10
#define NH    8
#define HD    32
#define NTOK  (HH*WW)            // 102400
#define NWIN  (32*32)            // 1024 windows
#define NN    (WIN*WIN)          // 100 tokens / window
#define MROWS NTOK
#define HID   1024
#define SCALE 0.17677669529663687f
#define LNEPS 1e-5f

typedef __nv_bfloat16 bf16;

// ---------------- scratch (static device, no allocations) ----------------
__device__ bf16  g_win[MROWS*DIM];    // LN1 out (bf16, window order)
__device__ float g_q  [MROWS*DIM];    // Q (scaled, fp32)
__device__ float g_kv [MROWS*2*DIM];  // K | V (fp32)
__device__ bf16  g_o  [MROWS*DIM];    // attention out (bf16, window order)
__device__ float g_x2 [MROWS*DIM];    // x + attn branch (fp32, token order)
__device__ bf16  g_h2 [MROWS*DIM];    // LN2 out (bf16)
__device__ bf16  g_f  [MROWS*HID];    // gelu(h2@l1+b) (bf16, NHWC)
__device__ bf16  g_f2 [MROWS*HID];    // gelu(dwconv(f)+b) (bf16)

// packed weights: word = bf16x2 (W[2k2,n], W[2k2+1,n]); layout [K/2][Nout]
__device__ unsigned p_qkv [128*768];   // wq | wkv fused
__device__ unsigned p_proj[128*256];
__device__ unsigned p_l1  [128*1024];
__device__ unsigned p_l2  [512*256];

__device__ __forceinline__ float gelu_exact(float v) {
    return 0.5f * v * (1.0f + erff(v * 0.70710678118654752f));
}
__device__ __forceinline__ unsigned packbf(float a, float b) {
    __nv_bfloat162 t = __floats2bfloat162_rn(a, b);
    return *(unsigned*)&t;
}
__device__ __forceinline__ void mma_bf16(float c[4], unsigned a0, unsigned a1,
                                         unsigned a2, unsigned a3,
                                         unsigned b0, unsigned b1) {
    asm volatile("mma.sync.aligned.m16n8k16.row.col.f32.bf16.bf16.f32 "
                 "{%0,%1,%2,%3}, {%4,%5,%6,%7}, {%8,%9}, {%0,%1,%2,%3};"
                 : "+f"(c[0]), "+f"(c[1]), "+f"(c[2]), "+f"(c[3])
                 : "r"(a0), "r"(a1), "r"(a2), "r"(a3), "r"(b0), "r"(b1));
}
__device__ __forceinline__ void cp16(void* smem, const void* g) {
    unsigned s = (unsigned)__cvta_generic_to_shared(smem);
    asm volatile("cp.async.cg.shared.global [%0], [%1], 16;" :: "r"(s), "l"(g));
}
__device__ __forceinline__ void ldm_x4(unsigned& r0, unsigned& r1, unsigned& r2,
                                       unsigned& r3, const void* p) {
    unsigned s = (unsigned)__cvta_generic_to_shared(p);
    asm volatile("ldmatrix.sync.aligned.m8n8.x4.shared.b16 {%0,%1,%2,%3}, [%4];"
                 : "=r"(r0), "=r"(r1), "=r"(r2), "=r"(r3) : "r"(s));
}

// ---------------- weight pack: [K,N] f32 -> words at [k2][ooff+n], row stride ostride ----
__global__ void pack_w(const float* __restrict__ W, unsigned* __restrict__ out,
                       int K2, int N, int ostride, int ooff) {
    int i = blockIdx.x * 256 + threadIdx.x;
    if (i >= K2 * N) return;
    int k2 = i / N, n = i - k2 * N;
    out[(size_t)k2 * ostride + ooff + n] =
        packbf(W[(size_t)(2 * k2) * N + n], W[(size_t)(2 * k2 + 1) * N + n]);
}

// ---------------- LayerNorm ----------------
__device__ __forceinline__ void ln_core(float v, const float* __restrict__ g,
                                        const float* __restrict__ b, int tid, float& y) {
    float s = v, ss = v * v;
    #pragma unroll
    for (int o = 16; o; o >>= 1) {
        s  += __shfl_xor_sync(0xffffffffu, s,  o);
        ss += __shfl_xor_sync(0xffffffffu, ss, o);
    }
    __shared__ float sh[8], sh2[8];
    int warp = tid >> 5, lane = tid & 31;
    if (lane == 0) { sh[warp] = s; sh2[warp] = ss; }
    __syncthreads();
    float ts = 0.f, tss = 0.f;
    #pragma unroll
    for (int i = 0; i < 8; i++) { ts += sh[i]; tss += sh2[i]; }
    float mean = ts * (1.0f / DIM);
    float var  = tss * (1.0f / DIM) - mean * mean;
    y = (v - mean) * rsqrtf(var + LNEPS) * g[tid] + b[tid];
}

__global__ void ln1_kernel(const float* __restrict__ x,
                           const float* __restrict__ g, const float* __restrict__ b) {
    int t = blockIdx.x, tid = threadIdx.x;
    float v = x[(size_t)t * DIM + tid];
    float y; ln_core(v, g, b, tid, y);
    int h = t / WW, w = t - h * WW;
    int r = ((h / WIN) * 32 + (w / WIN)) * NN + (h % WIN) * WIN + (w % WIN);
    g_win[(size_t)r * DIM + tid] = __float2bfloat16(y);
}

__global__ void ln2_kernel(const float* __restrict__ g, const float* __restrict__ b) {
    int t = blockIdx.x, tid = threadIdx.x;
    float v = g_x2[(size_t)t * DIM + tid];
    float y; ln_core(v, g, b, tid, y);
    g_h2[(size_t)t * DIM + tid] = __float2bfloat16(y);
}

// ---------------- bf16 MMA GEMM, cp.async double-buffer + ldmatrix ----------------
// 128x128x32 tile, 256 threads, warp layout 2(M)x4(N), warp tile 64x32.
// MODE 0: g_win @ [wq|wkv] (N=768): c<256 -> g_q=(v+bq)*SCALE ; else g_kv=v+bkv
// MODE 2: g_o   @ proj -> g_x2, window reverse + residual x
// MODE 3: g_h2  @ l1   -> g_f (bf16), gelu
// MODE 4: g_f2  @ l2   -> out, + g_x2 residual
template<int MODE>
__launch_bounds__(256)
__global__ void tgemm(const unsigned* __restrict__ Bpk, const float* __restrict__ bias,
                      const float* __restrict__ bias2, const float* __restrict__ res,
                      float* __restrict__ Coutf, int Ndim, int Kdim) {
    const bf16* A;
    if constexpr (MODE == 0) A = g_win;
    else if constexpr (MODE == 2) A = g_o;
    else if constexpr (MODE == 3) A = g_h2;
    else A = g_f2;

    constexpr int AW = 20;    // words per A smem row (80B, conflict-free ldmatrix)
    constexpr int BW = 136;   // words per B smem row
    __shared__ unsigned As[2][128 * AW];
    __shared__ unsigned Bs[2][16 * BW];

    const int tid  = threadIdx.x;
    const int bx   = blockIdx.x, by = blockIdx.y;
    const int lane = tid & 31;
    const int warp = tid >> 5;
    const int warpM = warp & 1;
    const int warpN = warp >> 1;
    const int gid = lane >> 2;
    const int tig = lane & 3;

    const int tiles = Kdim / 32;

    float acc[4][4][4];
    #pragma unroll
    for (int i = 0; i < 4; i++)
        #pragma unroll
        for (int j = 0; j < 4; j++)
            #pragma unroll
            for (int r = 0; r < 4; r++) acc[i][j][r] = 0.f;

    // stage loader: A tile 128x32 bf16 (512 x 16B), B tile 16x128 words (512 x 16B)
    const int arow = tid >> 2, ac = tid & 3;            // +128 rows for second half
    const int brow = tid >> 5, bc = (tid & 31) << 2;    // +8 rows for second half
    const bf16*     Abase = A   + (size_t)(by * 128) * Kdim;
    const unsigned* Bbase = Bpk + (size_t)bx * 128;

#define LOAD_STAGE(T, ST)                                                           \
    {                                                                               \
        cp16(&As[ST][(arow)      * AW + ac * 4], Abase + (size_t)(arow)      * Kdim + (T) * 32 + ac * 8); \
        cp16(&As[ST][(arow + 64) * AW + ac * 4], Abase + (size_t)(arow + 64) * Kdim + (T) * 32 + ac * 8); \
        cp16(&Bs[ST][(brow)     * BW + bc], Bbase + (size_t)((T) * 16 + brow)     * Ndim + bc); \
        cp16(&Bs[ST][(brow + 8) * BW + bc], Bbase + (size_t)((T) * 16 + brow + 8) * Ndim + bc); \
        asm volatile("cp.async.commit_group;");                                     \
    }

    LOAD_STAGE(0, 0);

    for (int t = 0; t < tiles; t++) {
        asm volatile("cp.async.wait_group 0;");
        __syncthreads();
        if (t + 1 < tiles) LOAD_STAGE(t + 1, (t + 1) & 1);

        const unsigned* Ast = As[t & 1];
        const unsigned* Bst = Bs[t & 1];
        #pragma unroll
        for (int s = 0; s < 2; s++) {
            unsigned af[4][4], bfr[4][2];
            #pragma unroll
            for (int i = 0; i < 4; i++) {
                int rl = warpM * 64 + i * 16 + (lane & 15);
                ldm_x4(af[i][0], af[i][1], af[i][2], af[i][3],
                       Ast + rl * AW + (s * 2 + (lane >> 4)) * 4);
            }
            #pragma unroll
            for (int j = 0; j < 4; j++) {
                int n0 = warpN * 32 + j * 8;
                bfr[j][0] = Bst[(s * 8 + tig)     * BW + n0 + gid];
                bfr[j][1] = Bst[(s * 8 + tig + 4) * BW + n0 + gid];
            }
            #pragma unroll
            for (int i = 0; i < 4; i++)
                #pragma unroll
                for (int j = 0; j < 4; j++)
                    mma_bf16(acc[i][j], af[i][0], af[i][1], af[i][2], af[i][3],
                             bfr[j][0], bfr[j][1]);
        }
        __syncthreads();
    }

    // ---------------- epilogue ----------------
    const int rowBase = by * 128 + warpM * 64;
    const int colBase = bx * 128 + warpN * 32;
    #pragma unroll
    for (int i = 0; i < 4; i++) {
        #pragma unroll
        for (int j = 0; j < 4; j++) {
            #pragma unroll
            for (int half = 0; half < 2; half++) {
                int r = rowBase + i * 16 + gid + half * 8;
                int c = colBase + j * 8 + tig * 2;
                float a0 = acc[i][j][half * 2 + 0];
                float a1 = acc[i][j][half * 2 + 1];
                if constexpr (MODE == 0) {
                    if (c < 256) {
                        g_q[(size_t)r * DIM + c]     = (a0 + bias[c])     * SCALE;
                        g_q[(size_t)r * DIM + c + 1] = (a1 + bias[c + 1]) * SCALE;
                    } else {
                        int cc = c - 256;
                        g_kv[(size_t)r * (2 * DIM) + cc]     = a0 + bias2[cc];
                        g_kv[(size_t)r * (2 * DIM) + cc + 1] = a1 + bias2[cc + 1];
                    }
                } else if constexpr (MODE == 2) {
                    float v0 = a0 + bias[c], v1 = a1 + bias[c + 1];
                    int wwin = r / NN, p = r - wwin * NN;
                    int tok = ((wwin >> 5) * WIN + p / WIN) * WW + (wwin & 31) * WIN + (p % WIN);
                    g_x2[(size_t)tok * DIM + c]     = res[(size_t)tok * DIM + c]     + v0;
                    g_x2[(size_t)tok * DIM + c + 1] = res[(size_t)tok * DIM + c + 1] + v1;
                } else if constexpr (MODE == 3) {
                    g_f[(size_t)r * Ndim + c]     = __float2bfloat16(gelu_exact(a0 + bias[c]));
                    g_f[(size_t)r * Ndim + c + 1] = __float2bfloat16(gelu_exact(a1 + bias[c + 1]));
                } else {
                    Coutf[(size_t)r * Ndim + c]     = g_x2[(size_t)r * DIM + c]     + a0 + bias[c];
                    Coutf[(size_t)r * Ndim + c + 1] = g_x2[(size_t)r * DIM + c + 1] + a1 + bias[c + 1];
                }
            }
        }
    }
#undef LOAD_STAGE
}

// ---------------- Windowed attention: 1 block/(window,head), 128 threads, 1 thread/row ----
__global__ __launch_bounds__(128)
void attn_kernel(const float* __restrict__ rpb) {
    __shared__ float qs[NN][HD + 1];
    __shared__ float ks[NN][HD];
    __shared__ float vs[NN][HD];
    __shared__ float rs[361];

    int blk  = blockIdx.x;
    int w    = blk >> 3;
    int head = blk & 7;
    int tid  = threadIdx.x;

    for (int i = tid; i < 361; i += 128) rs[i] = rpb[i * NH + head];
    for (int i = tid; i < NN * HD; i += 128) {
        int n = i >> 5, d = i & 31;
        size_t base = (size_t)(w * NN + n);
        qs[n][d] = g_q [base * DIM + head * HD + d];
        ks[n][d] = g_kv[base * (2 * DIM) + head * HD + d];
        vs[n][d] = g_kv[base * (2 * DIM) + DIM + head * HD + d];
    }
    __syncthreads();

    int n = tid;
    if (n < NN) {
        float q[HD], acc[HD];
        #pragma unroll
        for (int d = 0; d < HD; d++) { q[d] = qs[n][d]; acc[d] = 0.f; }
        int cn = 19 * (n / 10) + (n % 10) + 180;
        float l = 0.f;
        int dm = 0, mj = 0;
        for (int m = 0; m < NN; m++) {
            float s = 0.f;
            #pragma unroll
            for (int d2 = 0; d2 < HD / 2; d2++) {
                float2 k2 = *(const float2*)&ks[m][2 * d2];
                s = fmaf(q[2 * d2],     k2.x, s);
                s = fmaf(q[2 * d2 + 1], k2.y, s);
            }
            // softmax is shift-invariant; scores are O(1) here, exp cannot overflow
            float p = __expf(s + rs[cn - dm]);
            l += p;
            #pragma unroll
            for (int d2 = 0; d2 < HD / 2; d2++) {
                float2 v2 = *(const float2*)&vs[m][2 * d2];
                acc[2 * d2]     = fmaf(p, v2.x, acc[2 * d2]);
                acc[2 * d2 + 1] = fmaf(p, v2.y, acc[2 * d2 + 1]);
            }
            dm++; mj++;
            if (mj == 10) { mj = 0; dm += 9; }
        }
        float inv = 1.0f / l;
        unsigned* op = (unsigned*)&g_o[((size_t)(w * NN + n)) * DIM + head * HD];
        #pragma unroll
        for (int d2 = 0; d2 < HD / 2; d2++)
            op[d2] = packbf(acc[2 * d2] * inv, acc[2 * d2 + 1] * inv);
    }
}

// ---------------- Depthwise 3x3 conv (NHWC, C=1024) + bias + gelu ----------------
__global__ __launch_bounds__(256)
void dwconv_kernel(const float* __restrict__ dw_w, const float* __restrict__ dw_b) {
    int c = blockIdx.x * 256 + threadIdx.x;
    int w = blockIdx.y;
    int h = blockIdx.z;
    float wk[9];
    #pragma unroll
    for (int t = 0; t < 9; t++) wk[t] = dw_w[c * 9 + t];
    float acc = dw_b[c];
    #pragma unroll
    for (int dh = -1; dh <= 1; dh++) {
        int hh = h + dh;
        if ((unsigned)hh >= HH) continue;
        #pragma unroll
        for (int dw2 = -1; dw2 <= 1; dw2++) {
            int ww2 = w + dw2;
            if ((unsigned)ww2 >= WW) continue;
            acc = fmaf(__bfloat162float(g_f[((size_t)hh * WW + ww2) * HID + c]),
                       wk[(dh + 1) * 3 + (dw2 + 1)], acc);
        }
    }
    g_f2[((size_t)h * WW + w) * HID + c] = __float2bfloat16(gelu_exact(acc));
}

// ---------------- launch ----------------
extern "C" void kernel_launch(void* const* d_in, const int* in_sizes, int n_in,
                              void* d_out, int out_size) {
    const float* x       = (const float*)d_in[0];
    const float* norm1_g = (const float*)d_in[1];
    const float* norm1_b = (const float*)d_in[2];
    const float* wq      = (const float*)d_in[3];
    const float* bq      = (const float*)d_in[4];
    const float* wkv     = (const float*)d_in[5];
    const float* bkv     = (const float*)d_in[6];
    const float* rpb     = (const float*)d_in[7];
    const float* proj_w  = (const float*)d_in[8];
    const float* proj_b  = (const float*)d_in[9];
    const float* norm2_g = (const float*)d_in[10];
    const float* norm2_b = (const float*)d_in[11];
    const float* l1_w    = (const float*)d_in[12];
    const float* l1_b    = (const float*)d_in[13];
    const float* dw_w    = (const float*)d_in[14];
    const float* dw_b    = (const float*)d_in[15];
    const float* l2_w    = (const float*)d_in[16];
    const float* l2_b    = (const float*)d_in[17];
    float* out = (float*)d_out;

    unsigned *pqkv, *pproj, *pl1, *pl2;
    cudaGetSymbolAddress((void**)&pqkv,  p_qkv);
    cudaGetSymbolAddress((void**)&pproj, p_proj);
    cudaGetSymbolAddress((void**)&pl1,   p_l1);
    cudaGetSymbolAddress((void**)&pl2,   p_l2);

    pack_w<<<(128*256  + 255)/256, 256>>>(wq,     pqkv,  128, 256,  768, 0);
    pack_w<<<(128*512  + 255)/256, 256>>>(wkv,    pqkv,  128, 512,  768, 256);
    pack_w<<<(128*256  + 255)/256, 256>>>(proj_w, pproj, 128, 256,  256, 0);
    pack_w<<<(128*1024 + 255)/256, 256>>>(l1_w,   pl1,   128, 1024, 1024, 0);
    pack_w<<<(512*256  + 255)/256, 256>>>(l2_w,   pl2,   512, 256,  256, 0);

    ln1_kernel<<<NTOK, 256>>>(x, norm1_g, norm1_b);
    tgemm<0><<<dim3(6, MROWS / 128), 256>>>(pqkv,  bq,     bkv,     nullptr, nullptr, 768,  DIM);
    attn_kernel<<<NWIN * NH, 128>>>(rpb);
    tgemm<2><<<dim3(2, MROWS / 128), 256>>>(pproj, proj_b, nullptr, x,       nullptr, DIM,  DIM);
    ln2_kernel<<<NTOK, 256>>>(norm2_g, norm2_b);
    tgemm<3><<<dim3(8, MROWS / 128), 256>>>(pl1,   l1_b,   nullptr, nullptr, nullptr, HID,  DIM);
    dwconv_kernel<<<dim3(HID / 256, WW, HH), 256>>>(dw_w, dw_b);
    tgemm<4><<<dim3(2, MROWS / 128), 256>>>(pl2,   l2_b,   nullptr, nullptr, out,     DIM,  HID);
}

// round 5
// speedup vs baseline: 3.8385x; 1.4404x over previous
#include <cuda_runtime.h>
#include <cuda_bf16.h>
#include <math.h>

// ---------------- problem constants ----------------
#define HH    320
#define WW    320
#define DIM   256
#define WIN   10
#define NH    8
#define HD    32
#define NTOK  (HH*WW)            // 102400
#define NWIN  (32*32)            // 1024
#define NN    (WIN*WIN)          // 100
#define MROWS NTOK
#define HID   1024
#define SCALE 0.17677669529663687f
#define LNEPS 1e-5f

typedef __nv_bfloat16 bf16;

// ---------------- scratch (words = bf16x2 unless noted) ----------------
__device__ unsigned g_winw[MROWS*128];   // LN1 out, window order
__device__ unsigned g_qw  [MROWS*128];   // Q (scaled)
__device__ unsigned g_kvw [MROWS*256];   // K | V
__device__ unsigned g_ow  [MROWS*128];   // attention out, window order
__device__ float    g_x2  [MROWS*256];   // x + attn branch (fp32, token order)
__device__ unsigned g_h2w [MROWS*128];   // LN2 out
__device__ unsigned g_fw  [MROWS*512];   // gelu(h2@l1+b), NHWC
__device__ unsigned g_f2w [MROWS*512];   // gelu(dwconv+b)

// packed weights: word = bf16x2 (W[2k2,n], W[2k2+1,n]); layout [K/2][Nout]
__device__ unsigned p_qkv [128*768];
__device__ unsigned p_proj[128*256];
__device__ unsigned p_l1  [128*1024];
__device__ unsigned p_l2  [512*256];

__device__ __forceinline__ float gelu_exact(float v) {
    return 0.5f * v * (1.0f + erff(v * 0.70710678118654752f));
}
__device__ __forceinline__ unsigned packbf(float a, float b) {
    __nv_bfloat162 t = __floats2bfloat162_rn(a, b);
    return *(unsigned*)&t;
}
__device__ __forceinline__ float2 unpackbf(unsigned u) {
    return __bfloat1622float2(*(__nv_bfloat162*)&u);
}
__device__ __forceinline__ void mma_bf16(float c[4], unsigned a0, unsigned a1,
                                         unsigned a2, unsigned a3,
                                         unsigned b0, unsigned b1) {
    asm volatile("mma.sync.aligned.m16n8k16.row.col.f32.bf16.bf16.f32 "
                 "{%0,%1,%2,%3}, {%4,%5,%6,%7}, {%8,%9}, {%0,%1,%2,%3};"
                 : "+f"(c[0]), "+f"(c[1]), "+f"(c[2]), "+f"(c[3])
                 : "r"(a0), "r"(a1), "r"(a2), "r"(a3), "r"(b0), "r"(b1));
}
__device__ __forceinline__ void cp16(void* smem, const void* g) {
    unsigned s = (unsigned)__cvta_generic_to_shared(smem);
    asm volatile("cp.async.cg.shared.global [%0], [%1], 16;" :: "r"(s), "l"(g));
}
__device__ __forceinline__ void ldm_x4(unsigned& r0, unsigned& r1, unsigned& r2,
                                       unsigned& r3, const void* p) {
    unsigned s = (unsigned)__cvta_generic_to_shared(p);
    asm volatile("ldmatrix.sync.aligned.m8n8.x4.shared.b16 {%0,%1,%2,%3}, [%4];"
                 : "=r"(r0), "=r"(r1), "=r"(r2), "=r"(r3) : "r"(s));
}

// ---------------- fused weight pack (one launch) ----------------
__global__ void pack_all(const float* __restrict__ wq, const float* __restrict__ wkv,
                         const float* __restrict__ proj_w, const float* __restrict__ l1_w,
                         const float* __restrict__ l2_w) {
    int i = blockIdx.x * 256 + threadIdx.x;
    if (i < 32768) {                       // wq -> p_qkv[:, 0:256]
        int k2 = i >> 8, n = i & 255;
        p_qkv[k2 * 768 + n] = packbf(wq[(2 * k2) * 256 + n], wq[(2 * k2 + 1) * 256 + n]);
    } else if (i < 98304) {                // wkv -> p_qkv[:, 256:768]
        int j = i - 32768, k2 = j >> 9, n = j & 511;
        p_qkv[k2 * 768 + 256 + n] = packbf(wkv[(2 * k2) * 512 + n], wkv[(2 * k2 + 1) * 512 + n]);
    } else if (i < 131072) {               // proj
        int j = i - 98304, k2 = j >> 8, n = j & 255;
        p_proj[j] = packbf(proj_w[(2 * k2) * 256 + n], proj_w[(2 * k2 + 1) * 256 + n]);
    } else if (i < 262144) {               // l1
        int j = i - 131072, k2 = j >> 10, n = j & 1023;
        p_l1[j] = packbf(l1_w[(2 * k2) * 1024 + n], l1_w[(2 * k2 + 1) * 1024 + n]);
    } else if (i < 393216) {               // l2 (K2=512)
        int j = i - 262144, k2 = j >> 8, n = j & 255;
        p_l2[j] = packbf(l2_w[(2 * k2) * 256 + n], l2_w[(2 * k2 + 1) * 256 + n]);
    }
}

// ---------------- LayerNorm: warp per token ----------------
template<int M>   // M=0: x -> g_winw (window perm); M=1: g_x2 -> g_h2w
__global__ __launch_bounds__(256)
void ln_kernel(const float* __restrict__ xin,
               const float* __restrict__ g, const float* __restrict__ b) {
    int warp = threadIdx.x >> 5, lane = threadIdx.x & 31;
    int t = blockIdx.x * 8 + warp;
    const float* src = (M == 0) ? xin : g_x2;
    const float4* xp = (const float4*)(src + (size_t)t * DIM) + lane * 2;
    float4 f0 = xp[0], f1 = xp[1];
    float s  = f0.x + f0.y + f0.z + f0.w + f1.x + f1.y + f1.z + f1.w;
    float ss = f0.x*f0.x + f0.y*f0.y + f0.z*f0.z + f0.w*f0.w
             + f1.x*f1.x + f1.y*f1.y + f1.z*f1.z + f1.w*f1.w;
    #pragma unroll
    for (int o = 16; o; o >>= 1) {
        s  += __shfl_xor_sync(0xffffffffu, s,  o);
        ss += __shfl_xor_sync(0xffffffffu, ss, o);
    }
    float mean = s * (1.0f / DIM);
    float rstd = rsqrtf(ss * (1.0f / DIM) - mean * mean + LNEPS);
    const float4* gp = (const float4*)g + lane * 2;
    const float4* bp = (const float4*)b + lane * 2;
    float4 g0 = gp[0], g1 = gp[1], b0 = bp[0], b1 = bp[1];
    unsigned w0 = packbf((f0.x-mean)*rstd*g0.x + b0.x, (f0.y-mean)*rstd*g0.y + b0.y);
    unsigned w1 = packbf((f0.z-mean)*rstd*g0.z + b0.z, (f0.w-mean)*rstd*g0.w + b0.w);
    unsigned w2 = packbf((f1.x-mean)*rstd*g1.x + b1.x, (f1.y-mean)*rstd*g1.y + b1.y);
    unsigned w3 = packbf((f1.z-mean)*rstd*g1.z + b1.z, (f1.w-mean)*rstd*g1.w + b1.w);
    size_t r;
    if constexpr (M == 0) {
        int h = t / WW, w = t - h * WW;
        r = ((h / WIN) * 32 + (w / WIN)) * NN + (h % WIN) * WIN + (w % WIN);
    } else r = t;
    unsigned* dst = (M == 0) ? g_winw : g_h2w;
    *(uint4*)&dst[r * 128 + lane * 4] = make_uint4(w0, w1, w2, w3);
}

// ---------------- bf16 MMA GEMM, 3-stage cp.async + swizzled smem ----------------
// 128x128x32 tile, 256 threads, warp 2(M)x4(N), warp tile 64x32.
// A smem: 16 words/row, chunk ^((row>>1)&3). B smem: 128 words/row, n ^((row&7)<<3).
template<int MODE>
__launch_bounds__(256)
__global__ void tgemm(const unsigned* __restrict__ Bpk, const float* __restrict__ bias,
                      const float* __restrict__ bias2, const float* __restrict__ res,
                      float* __restrict__ Coutf, int Ndim, int Kdim) {
    const bf16* A;
    if constexpr (MODE == 0) A = (const bf16*)g_winw;
    else if constexpr (MODE == 2) A = (const bf16*)g_ow;
    else if constexpr (MODE == 3) A = (const bf16*)g_h2w;
    else A = (const bf16*)g_f2w;

    __shared__ unsigned As[3][128 * 16];
    __shared__ unsigned Bs[3][16 * 128];

    const int tid  = threadIdx.x;
    const int bx   = blockIdx.x, by = blockIdx.y;
    const int lane = tid & 31;
    const int warp = tid >> 5;
    const int warpM = warp & 1;
    const int warpN = warp >> 1;
    const int gid = lane >> 2;
    const int tig = lane & 3;

    const int tiles = Kdim / 32;

    float acc[4][4][4];
    #pragma unroll
    for (int i = 0; i < 4; i++)
        #pragma unroll
        for (int j = 0; j < 4; j++)
            #pragma unroll
            for (int r = 0; r < 4; r++) acc[i][j][r] = 0.f;

    const int arow = tid >> 2, ac = tid & 3;
    const int brow = tid >> 5, bc = (tid & 31) << 2;
    const int aoff = arow * 16 + ((ac ^ ((arow >> 1) & 3)) << 2);
    const int boff = brow * 128 + (bc ^ (brow << 3));
    const bf16*     Abase = A   + (size_t)(by * 128) * Kdim;
    const unsigned* Bbase = Bpk + (size_t)bx * 128;

#define LOAD_STAGE(T, ST)                                                                         \
    {                                                                                             \
        cp16(&As[ST][aoff],            Abase + (size_t)(arow)      * Kdim + (T) * 32 + ac * 8);   \
        cp16(&As[ST][aoff + 64 * 16],  Abase + (size_t)(arow + 64) * Kdim + (T) * 32 + ac * 8);   \
        cp16(&Bs[ST][boff],            Bbase + (size_t)((T) * 16 + brow)     * Ndim + bc);        \
        cp16(&Bs[ST][boff + 8 * 128],  Bbase + (size_t)((T) * 16 + brow + 8) * Ndim + bc);        \
        asm volatile("cp.async.commit_group;");                                                   \
    }

    LOAD_STAGE(0, 0);
    if (tiles > 1) LOAD_STAGE(1, 1);

    const int rbase = warpM * 64 + (lane & 15);
    const int km    = (rbase >> 1) & 3;
    const int cbit  = lane >> 4;
    const int nb    = warpN * 32 + gid;
    const int xr1   = tig << 3;
    const int xr2   = (tig + 4) << 3;

    int sc = 0;
    for (int t = 0; t < tiles; t++) {
        asm volatile("cp.async.wait_group 1;");
        __syncthreads();
        if (t + 2 < tiles) {
            int s2 = sc + 2; if (s2 >= 3) s2 -= 3;
            LOAD_STAGE(t + 2, s2);
        }

        const unsigned* Ast = As[sc];
        const unsigned* Bst = Bs[sc];
        #pragma unroll
        for (int s = 0; s < 2; s++) {
            const int aswz = ((s * 2 + cbit) ^ km) << 2;
            unsigned af[4][4], bfr[4][2];
            #pragma unroll
            for (int i = 0; i < 4; i++)
                ldm_x4(af[i][0], af[i][1], af[i][2], af[i][3],
                       Ast + (rbase + i * 16) * 16 + aswz);
            const int r1 = (s * 8 + tig) * 128, r2 = (s * 8 + tig + 4) * 128;
            #pragma unroll
            for (int j = 0; j < 4; j++) {
                int n = nb + j * 8;
                bfr[j][0] = Bst[r1 + (n ^ xr1)];
                bfr[j][1] = Bst[r2 + (n ^ xr2)];
            }
            #pragma unroll
            for (int i = 0; i < 4; i++)
                #pragma unroll
                for (int j = 0; j < 4; j++)
                    mma_bf16(acc[i][j], af[i][0], af[i][1], af[i][2], af[i][3],
                             bfr[j][0], bfr[j][1]);
        }
        __syncthreads();
        sc++; if (sc == 3) sc = 0;
    }
#undef LOAD_STAGE

    const int rowBase = by * 128 + warpM * 64;
    const int colBase = bx * 128 + warpN * 32;
    #pragma unroll
    for (int i = 0; i < 4; i++) {
        #pragma unroll
        for (int j = 0; j < 4; j++) {
            #pragma unroll
            for (int half = 0; half < 2; half++) {
                int r = rowBase + i * 16 + gid + half * 8;
                int c = colBase + j * 8 + tig * 2;
                float a0 = acc[i][j][half * 2 + 0];
                float a1 = acc[i][j][half * 2 + 1];
                if constexpr (MODE == 0) {
                    if (c < 256) {
                        g_qw[(size_t)r * 128 + (c >> 1)] =
                            packbf((a0 + bias[c]) * SCALE, (a1 + bias[c + 1]) * SCALE);
                    } else {
                        int cc = c - 256;
                        g_kvw[(size_t)r * 256 + (cc >> 1)] =
                            packbf(a0 + bias2[cc], a1 + bias2[cc + 1]);
                    }
                } else if constexpr (MODE == 2) {
                    float v0 = a0 + bias[c], v1 = a1 + bias[c + 1];
                    int wwin = r / NN, p = r - wwin * NN;
                    int tok = ((wwin >> 5) * WIN + p / WIN) * WW + (wwin & 31) * WIN + (p % WIN);
                    g_x2[(size_t)tok * DIM + c]     = res[(size_t)tok * DIM + c]     + v0;
                    g_x2[(size_t)tok * DIM + c + 1] = res[(size_t)tok * DIM + c + 1] + v1;
                } else if constexpr (MODE == 3) {
                    g_fw[(size_t)r * 512 + (c >> 1)] =
                        packbf(gelu_exact(a0 + bias[c]), gelu_exact(a1 + bias[c + 1]));
                } else {
                    Coutf[(size_t)r * Ndim + c]     = g_x2[(size_t)r * DIM + c]     + a0 + bias[c];
                    Coutf[(size_t)r * Ndim + c + 1] = g_x2[(size_t)r * DIM + c + 1] + a1 + bias[c + 1];
                }
            }
        }
    }
}

// ---------------- Windowed attention ----------------
__global__ __launch_bounds__(128)
void attn_kernel(const float* __restrict__ rpb) {
    __shared__ float qs[NN][HD + 1];
    __shared__ float ks[NN][HD];
    __shared__ float vs[NN][HD];
    __shared__ float rs[361];

    int blk  = blockIdx.x;
    int w    = blk >> 3;
    int head = blk & 7;
    int tid  = threadIdx.x;

    for (int i = tid; i < 361; i += 128) rs[i] = rpb[i * NH + head];
    for (int i = tid; i < NN * 16; i += 128) {
        int n = i >> 4, d2 = i & 15;
        size_t base = (size_t)(w * NN + n);
        float2 qv = unpackbf(g_qw [base * 128 + head * 16 + d2]);
        float2 kv = unpackbf(g_kvw[base * 256 + head * 16 + d2]);
        float2 vv = unpackbf(g_kvw[base * 256 + 128 + head * 16 + d2]);
        qs[n][2*d2] = qv.x; qs[n][2*d2+1] = qv.y;
        ks[n][2*d2] = kv.x; ks[n][2*d2+1] = kv.y;
        vs[n][2*d2] = vv.x; vs[n][2*d2+1] = vv.y;
    }
    __syncthreads();

    int n = tid;
    if (n < NN) {
        float q[HD], acc[HD];
        #pragma unroll
        for (int d = 0; d < HD; d++) { q[d] = qs[n][d]; acc[d] = 0.f; }
        int cn = 19 * (n / 10) + (n % 10) + 180;
        float l = 0.f;
        int dm = 0, mj = 0;
        for (int m = 0; m < NN; m++) {
            const float4* kp = (const float4*)&ks[m][0];
            float s = 0.f;
            #pragma unroll
            for (int dd = 0; dd < 8; dd++) {
                float4 k4 = kp[dd];
                s = fmaf(q[4*dd],   k4.x, s);
                s = fmaf(q[4*dd+1], k4.y, s);
                s = fmaf(q[4*dd+2], k4.z, s);
                s = fmaf(q[4*dd+3], k4.w, s);
            }
            float p = __expf(s + rs[cn - dm]);   // shift-invariant, scores O(1)
            l += p;
            const float4* vp = (const float4*)&vs[m][0];
            #pragma unroll
            for (int dd = 0; dd < 8; dd++) {
                float4 v4 = vp[dd];
                acc[4*dd]   = fmaf(p, v4.x, acc[4*dd]);
                acc[4*dd+1] = fmaf(p, v4.y, acc[4*dd+1]);
                acc[4*dd+2] = fmaf(p, v4.z, acc[4*dd+2]);
                acc[4*dd+3] = fmaf(p, v4.w, acc[4*dd+3]);
            }
            dm++; mj++;
            if (mj == 10) { mj = 0; dm += 9; }
        }
        float inv = 1.0f / l;
        unsigned* op = &g_ow[((size_t)(w * NN + n)) * 128 + head * 16];
        #pragma unroll
        for (int d2 = 0; d2 < 16; d2++)
            op[d2] = packbf(acc[2*d2] * inv, acc[2*d2+1] * inv);
    }
}

// ---------------- Depthwise 3x3 conv: channel-pair threads, h-loop reg ring ----------
__global__ __launch_bounds__(128)
void dwconv_kernel(const float* __restrict__ dw_w, const float* __restrict__ dw_b) {
    int c2 = blockIdx.x * 128 + threadIdx.x;   // 0..511
    int w  = blockIdx.y;
    int ca = 2 * c2, cb = 2 * c2 + 1;
    float wka[9], wkb[9];
    #pragma unroll
    for (int t = 0; t < 9; t++) { wka[t] = dw_w[ca * 9 + t]; wkb[t] = dw_w[cb * 9 + t]; }
    float ba = dw_b[ca], bb = dw_b[cb];
    bool vL = (w > 0), vR = (w < WW - 1);

    float2 row[3][3];
    #pragma unroll
    for (int a = 0; a < 3; a++)
        #pragma unroll
        for (int bz = 0; bz < 3; bz++) row[a][bz] = make_float2(0.f, 0.f);

    auto LD = [&](int hh, int wp, bool v) -> float2 {
        if (!v) return make_float2(0.f, 0.f);
        return unpackbf(g_fw[((size_t)hh * WW + wp) * 512 + c2]);
    };
    row[1][0] = LD(0, w - 1, vL); row[1][1] = LD(0, w, true); row[1][2] = LD(0, w + 1, vR);
    row[2][0] = LD(1, w - 1, vL); row[2][1] = LD(1, w, true); row[2][2] = LD(1, w + 1, vR);

    for (int h = 0; h < HH; h++) {
        float oa = ba, ob = bb;
        #pragma unroll
        for (int ri = 0; ri < 3; ri++)
            #pragma unroll
            for (int wi = 0; wi < 3; wi++) {
                oa = fmaf(row[ri][wi].x, wka[ri * 3 + wi], oa);
                ob = fmaf(row[ri][wi].y, wkb[ri * 3 + wi], ob);
            }
        g_f2w[((size_t)h * WW + w) * 512 + c2] = packbf(gelu_exact(oa), gelu_exact(ob));
        #pragma unroll
        for (int wi = 0; wi < 3; wi++) { row[0][wi] = row[1][wi]; row[1][wi] = row[2][wi]; }
        bool vH = (h + 2 < HH);
        row[2][0] = LD(h + 2, w - 1, vL && vH);
        row[2][1] = LD(h + 2, w,     vH);
        row[2][2] = LD(h + 2, w + 1, vR && vH);
    }
}

// ---------------- launch ----------------
extern "C" void kernel_launch(void* const* d_in, const int* in_sizes, int n_in,
                              void* d_out, int out_size) {
    const float* x       = (const float*)d_in[0];
    const float* norm1_g = (const float*)d_in[1];
    const float* norm1_b = (const float*)d_in[2];
    const float* wq      = (const float*)d_in[3];
    const float* bq      = (const float*)d_in[4];
    const float* wkv     = (const float*)d_in[5];
    const float* bkv     = (const float*)d_in[6];
    const float* rpb     = (const float*)d_in[7];
    const float* proj_w  = (const float*)d_in[8];
    const float* proj_b  = (const float*)d_in[9];
    const float* norm2_g = (const float*)d_in[10];
    const float* norm2_b = (const float*)d_in[11];
    const float* l1_w    = (const float*)d_in[12];
    const float* l1_b    = (const float*)d_in[13];
    const float* dw_w    = (const float*)d_in[14];
    const float* dw_b    = (const float*)d_in[15];
    const float* l2_w    = (const float*)d_in[16];
    const float* l2_b    = (const float*)d_in[17];
    float* out = (float*)d_out;

    unsigned *pqkv, *pproj, *pl1, *pl2;
    cudaGetSymbolAddress((void**)&pqkv,  p_qkv);
    cudaGetSymbolAddress((void**)&pproj, p_proj);
    cudaGetSymbolAddress((void**)&pl1,   p_l1);
    cudaGetSymbolAddress((void**)&pl2,   p_l2);

    pack_all<<<1536, 256>>>(wq, wkv, proj_w, l1_w, l2_w);
    ln_kernel<0><<<NTOK / 8, 256>>>(x, norm1_g, norm1_b);
    tgemm<0><<<dim3(6, MROWS / 128), 256>>>(pqkv,  bq,     bkv,     nullptr, nullptr, 768, DIM);
    attn_kernel<<<NWIN * NH, 128>>>(rpb);
    tgemm<2><<<dim3(2, MROWS / 128), 256>>>(pproj, proj_b, nullptr, x,       nullptr, DIM, DIM);
    ln_kernel<1><<<NTOK / 8, 256>>>(nullptr, norm2_g, norm2_b);
    tgemm<3><<<dim3(8, MROWS / 128), 256>>>(pl1,   l1_b,   nullptr, nullptr, nullptr, HID, DIM);
    dwconv_kernel<<<dim3(4, WW), 128>>>(dw_w, dw_b);
    tgemm<4><<<dim3(2, MROWS / 128), 256>>>(pl2,   l2_b,   nullptr, nullptr, out,     DIM, HID);
}

// round 6
// speedup vs baseline: 4.9131x; 1.2799x over previous
#include <cuda_runtime.h>
#include <cuda_bf16.h>
#include <math.h>

// ---------------- problem constants ----------------
#define HH    320
#define WW    320
#define DIM   256
#define WIN   10
#define NH    8
#define HD    32
#define NTOK  (HH*WW)            // 102400
#define NWIN  (32*32)            // 1024
#define NN    (WIN*WIN)          // 100
#define MROWS NTOK
#define HID   1024
#define SCALE 0.17677669529663687f
#define LNEPS 1e-5f

typedef __nv_bfloat16 bf16;

// ---------------- scratch (words = bf16x2 unless noted) ----------------
__device__ unsigned g_winw[MROWS*128];   // LN1 out, window order
__device__ unsigned g_qw  [MROWS*128];   // Q (scaled)
__device__ unsigned g_kvw [MROWS*256];   // K | V
__device__ unsigned g_ow  [MROWS*128];   // attention out, window order
__device__ float    g_x2  [MROWS*256];   // x + attn branch (fp32, token order)
__device__ unsigned g_h2w [MROWS*128];   // LN2 out
__device__ unsigned g_fw  [MROWS*512];   // gelu(h2@l1+b), NHWC
__device__ unsigned g_f2w [MROWS*512];   // gelu(dwconv+b)

// packed weights: word = bf16x2 (W[2k2,n], W[2k2+1,n]); layout [K/2][Nout]
__device__ unsigned p_qkv [128*768];
__device__ unsigned p_proj[128*256];
__device__ unsigned p_l1  [128*1024];
__device__ unsigned p_l2  [512*256];

__device__ __forceinline__ float gelu_exact(float v) {
    return 0.5f * v * (1.0f + erff(v * 0.70710678118654752f));
}
__device__ __forceinline__ unsigned packbf(float a, float b) {
    __nv_bfloat162 t = __floats2bfloat162_rn(a, b);
    return *(unsigned*)&t;
}
__device__ __forceinline__ float2 unpackbf(unsigned u) {
    return __bfloat1622float2(*(__nv_bfloat162*)&u);
}
__device__ __forceinline__ void mma_bf16(float c[4], unsigned a0, unsigned a1,
                                         unsigned a2, unsigned a3,
                                         unsigned b0, unsigned b1) {
    asm volatile("mma.sync.aligned.m16n8k16.row.col.f32.bf16.bf16.f32 "
                 "{%0,%1,%2,%3}, {%4,%5,%6,%7}, {%8,%9}, {%0,%1,%2,%3};"
                 : "+f"(c[0]), "+f"(c[1]), "+f"(c[2]), "+f"(c[3])
                 : "r"(a0), "r"(a1), "r"(a2), "r"(a3), "r"(b0), "r"(b1));
}
__device__ __forceinline__ void cp16(void* smem, const void* g) {
    unsigned s = (unsigned)__cvta_generic_to_shared(smem);
    asm volatile("cp.async.cg.shared.global [%0], [%1], 16;" :: "r"(s), "l"(g));
}
__device__ __forceinline__ void ldm_x4(unsigned& r0, unsigned& r1, unsigned& r2,
                                       unsigned& r3, const void* p) {
    unsigned s = (unsigned)__cvta_generic_to_shared(p);
    asm volatile("ldmatrix.sync.aligned.m8n8.x4.shared.b16 {%0,%1,%2,%3}, [%4];"
                 : "=r"(r0), "=r"(r1), "=r"(r2), "=r"(r3) : "r"(s));
}
__device__ __forceinline__ void ldm_x4t(unsigned& r0, unsigned& r1, unsigned& r2,
                                        unsigned& r3, const void* p) {
    unsigned s = (unsigned)__cvta_generic_to_shared(p);
    asm volatile("ldmatrix.sync.aligned.m8n8.x4.trans.shared.b16 {%0,%1,%2,%3}, [%4];"
                 : "=r"(r0), "=r"(r1), "=r"(r2), "=r"(r3) : "r"(s));
}

// ---------------- fused weight pack ----------------
__global__ void pack_all(const float* __restrict__ wq, const float* __restrict__ wkv,
                         const float* __restrict__ proj_w, const float* __restrict__ l1_w,
                         const float* __restrict__ l2_w) {
    int i = blockIdx.x * 256 + threadIdx.x;
    if (i < 32768) {
        int k2 = i >> 8, n = i & 255;
        p_qkv[k2 * 768 + n] = packbf(wq[(2 * k2) * 256 + n], wq[(2 * k2 + 1) * 256 + n]);
    } else if (i < 98304) {
        int j = i - 32768, k2 = j >> 9, n = j & 511;
        p_qkv[k2 * 768 + 256 + n] = packbf(wkv[(2 * k2) * 512 + n], wkv[(2 * k2 + 1) * 512 + n]);
    } else if (i < 131072) {
        int j = i - 98304, k2 = j >> 8, n = j & 255;
        p_proj[j] = packbf(proj_w[(2 * k2) * 256 + n], proj_w[(2 * k2 + 1) * 256 + n]);
    } else if (i < 262144) {
        int j = i - 131072, k2 = j >> 10, n = j & 1023;
        p_l1[j] = packbf(l1_w[(2 * k2) * 1024 + n], l1_w[(2 * k2 + 1) * 1024 + n]);
    } else if (i < 393216) {
        int j = i - 262144, k2 = j >> 8, n = j & 255;
        p_l2[j] = packbf(l2_w[(2 * k2) * 256 + n], l2_w[(2 * k2 + 1) * 256 + n]);
    }
}

// ---------------- LayerNorm: warp per token ----------------
template<int M>   // M=0: x -> g_winw (window perm); M=1: g_x2 -> g_h2w
__global__ __launch_bounds__(256)
void ln_kernel(const float* __restrict__ xin,
               const float* __restrict__ g, const float* __restrict__ b) {
    int warp = threadIdx.x >> 5, lane = threadIdx.x & 31;
    int t = blockIdx.x * 8 + warp;
    const float* src = (M == 0) ? xin : g_x2;
    const float4* xp = (const float4*)(src + (size_t)t * DIM) + lane * 2;
    float4 f0 = xp[0], f1 = xp[1];
    float s  = f0.x + f0.y + f0.z + f0.w + f1.x + f1.y + f1.z + f1.w;
    float ss = f0.x*f0.x + f0.y*f0.y + f0.z*f0.z + f0.w*f0.w
             + f1.x*f1.x + f1.y*f1.y + f1.z*f1.z + f1.w*f1.w;
    #pragma unroll
    for (int o = 16; o; o >>= 1) {
        s  += __shfl_xor_sync(0xffffffffu, s,  o);
        ss += __shfl_xor_sync(0xffffffffu, ss, o);
    }
    float mean = s * (1.0f / DIM);
    float rstd = rsqrtf(ss * (1.0f / DIM) - mean * mean + LNEPS);
    const float4* gp = (const float4*)g + lane * 2;
    const float4* bp = (const float4*)b + lane * 2;
    float4 g0 = gp[0], g1 = gp[1], b0 = bp[0], b1 = bp[1];
    unsigned w0 = packbf((f0.x-mean)*rstd*g0.x + b0.x, (f0.y-mean)*rstd*g0.y + b0.y);
    unsigned w1 = packbf((f0.z-mean)*rstd*g0.z + b0.z, (f0.w-mean)*rstd*g0.w + b0.w);
    unsigned w2 = packbf((f1.x-mean)*rstd*g1.x + b1.x, (f1.y-mean)*rstd*g1.y + b1.y);
    unsigned w3 = packbf((f1.z-mean)*rstd*g1.z + b1.z, (f1.w-mean)*rstd*g1.w + b1.w);
    size_t r;
    if constexpr (M == 0) {
        int h = t / WW, w = t - h * WW;
        r = ((h / WIN) * 32 + (w / WIN)) * NN + (h % WIN) * WIN + (w % WIN);
    } else r = t;
    unsigned* dst = (M == 0) ? g_winw : g_h2w;
    *(uint4*)&dst[r * 128 + lane * 4] = make_uint4(w0, w1, w2, w3);
}

// ---------------- bf16 MMA GEMM, 3-stage cp.async + swizzled smem ----------------
template<int MODE>
__launch_bounds__(256)
__global__ void tgemm(const unsigned* __restrict__ Bpk, const float* __restrict__ bias,
                      const float* __restrict__ bias2, const float* __restrict__ res,
                      float* __restrict__ Coutf, int Ndim, int Kdim) {
    const bf16* A;
    if constexpr (MODE == 0) A = (const bf16*)g_winw;
    else if constexpr (MODE == 2) A = (const bf16*)g_ow;
    else if constexpr (MODE == 3) A = (const bf16*)g_h2w;
    else A = (const bf16*)g_f2w;

    __shared__ unsigned As[3][128 * 16];
    __shared__ unsigned Bs[3][16 * 128];

    const int tid  = threadIdx.x;
    const int bx   = blockIdx.x, by = blockIdx.y;
    const int lane = tid & 31;
    const int warp = tid >> 5;
    const int warpM = warp & 1;
    const int warpN = warp >> 1;
    const int gid = lane >> 2;
    const int tig = lane & 3;

    const int tiles = Kdim / 32;

    float acc[4][4][4];
    #pragma unroll
    for (int i = 0; i < 4; i++)
        #pragma unroll
        for (int j = 0; j < 4; j++)
            #pragma unroll
            for (int r = 0; r < 4; r++) acc[i][j][r] = 0.f;

    const int arow = tid >> 2, ac = tid & 3;
    const int brow = tid >> 5, bc = (tid & 31) << 2;
    const int aoff = arow * 16 + ((ac ^ ((arow >> 1) & 3)) << 2);
    const int boff = brow * 128 + (bc ^ (brow << 3));
    const bf16*     Abase = A   + (size_t)(by * 128) * Kdim;
    const unsigned* Bbase = Bpk + (size_t)bx * 128;

#define LOAD_STAGE(T, ST)                                                                         \
    {                                                                                             \
        cp16(&As[ST][aoff],            Abase + (size_t)(arow)      * Kdim + (T) * 32 + ac * 8);   \
        cp16(&As[ST][aoff + 64 * 16],  Abase + (size_t)(arow + 64) * Kdim + (T) * 32 + ac * 8);   \
        cp16(&Bs[ST][boff],            Bbase + (size_t)((T) * 16 + brow)     * Ndim + bc);        \
        cp16(&Bs[ST][boff + 8 * 128],  Bbase + (size_t)((T) * 16 + brow + 8) * Ndim + bc);        \
        asm volatile("cp.async.commit_group;");                                                   \
    }

    LOAD_STAGE(0, 0);
    if (tiles > 1) LOAD_STAGE(1, 1);

    const int rbase = warpM * 64 + (lane & 15);
    const int km    = (rbase >> 1) & 3;
    const int cbit  = lane >> 4;
    const int nb    = warpN * 32 + gid;
    const int xr1   = tig << 3;
    const int xr2   = (tig + 4) << 3;

    int sc = 0;
    for (int t = 0; t < tiles; t++) {
        asm volatile("cp.async.wait_group 1;");
        __syncthreads();
        if (t + 2 < tiles) {
            int s2 = sc + 2; if (s2 >= 3) s2 -= 3;
            LOAD_STAGE(t + 2, s2);
        }

        const unsigned* Ast = As[sc];
        const unsigned* Bst = Bs[sc];
        #pragma unroll
        for (int s = 0; s < 2; s++) {
            const int aswz = ((s * 2 + cbit) ^ km) << 2;
            unsigned af[4][4], bfr[4][2];
            #pragma unroll
            for (int i = 0; i < 4; i++)
                ldm_x4(af[i][0], af[i][1], af[i][2], af[i][3],
                       Ast + (rbase + i * 16) * 16 + aswz);
            const int r1 = (s * 8 + tig) * 128, r2 = (s * 8 + tig + 4) * 128;
            #pragma unroll
            for (int j = 0; j < 4; j++) {
                int n = nb + j * 8;
                bfr[j][0] = Bst[r1 + (n ^ xr1)];
                bfr[j][1] = Bst[r2 + (n ^ xr2)];
            }
            #pragma unroll
            for (int i = 0; i < 4; i++)
                #pragma unroll
                for (int j = 0; j < 4; j++)
                    mma_bf16(acc[i][j], af[i][0], af[i][1], af[i][2], af[i][3],
                             bfr[j][0], bfr[j][1]);
        }
        __syncthreads();
        sc++; if (sc == 3) sc = 0;
    }
#undef LOAD_STAGE

    const int rowBase = by * 128 + warpM * 64;
    const int colBase = bx * 128 + warpN * 32;
    #pragma unroll
    for (int i = 0; i < 4; i++) {
        #pragma unroll
        for (int j = 0; j < 4; j++) {
            #pragma unroll
            for (int half = 0; half < 2; half++) {
                int r = rowBase + i * 16 + gid + half * 8;
                int c = colBase + j * 8 + tig * 2;
                float a0 = acc[i][j][half * 2 + 0];
                float a1 = acc[i][j][half * 2 + 1];
                if constexpr (MODE == 0) {
                    if (c < 256) {
                        g_qw[(size_t)r * 128 + (c >> 1)] =
                            packbf((a0 + bias[c]) * SCALE, (a1 + bias[c + 1]) * SCALE);
                    } else {
                        int cc = c - 256;
                        g_kvw[(size_t)r * 256 + (cc >> 1)] =
                            packbf(a0 + bias2[cc], a1 + bias2[cc + 1]);
                    }
                } else if constexpr (MODE == 2) {
                    float v0 = a0 + bias[c], v1 = a1 + bias[c + 1];
                    int wwin = r / NN, p = r - wwin * NN;
                    int tok = ((wwin >> 5) * WIN + p / WIN) * WW + (wwin & 31) * WIN + (p % WIN);
                    g_x2[(size_t)tok * DIM + c]     = res[(size_t)tok * DIM + c]     + v0;
                    g_x2[(size_t)tok * DIM + c + 1] = res[(size_t)tok * DIM + c + 1] + v1;
                } else if constexpr (MODE == 3) {
                    g_fw[(size_t)r * 512 + (c >> 1)] =
                        packbf(gelu_exact(a0 + bias[c]), gelu_exact(a1 + bias[c + 1]));
                } else {
                    Coutf[(size_t)r * Ndim + c]     = g_x2[(size_t)r * DIM + c]     + a0 + bias[c];
                    Coutf[(size_t)r * Ndim + c + 1] = g_x2[(size_t)r * DIM + c + 1] + a1 + bias[c + 1];
                }
            }
        }
    }
}

// ---------------- Windowed attention via tensor cores ----------------
// Block = (window, head), 4 warps. Q/K/V head slice in smem [112][40] bf16 (80B rows,
// conflict-free ldmatrix; rows 100-111 zero). Warp handles m-tiles {warp, warp+4}.
// S = Q@K^T (m16n8k16, K via non-trans ldmatrix = B-frag), +rpb, exp (no max-sub),
// P repacked in-register to A-frags, PV with V via ldmatrix.trans B-frags.
__global__ __launch_bounds__(128)
void attn_mma(const float* __restrict__ rpb) {
    __shared__ bf16 qs[112][40];
    __shared__ bf16 ks[112][40];
    __shared__ bf16 vs[112][40];
    __shared__ float rs[361];

    const int blk  = blockIdx.x;
    const int w    = blk >> 3;
    const int head = blk & 7;
    const int tid  = threadIdx.x;
    const int warp = tid >> 5;
    const int lane = tid & 31;
    const int gid  = lane >> 2;
    const int tig  = lane & 3;

    for (int i = tid; i < 361; i += 128) rs[i] = rpb[i * NH + head];
    // load 112 tokens x 16 words each (pad tokens zero)
    for (int i = tid; i < 112 * 16; i += 128) {
        int n = i >> 4, d2 = i & 15;
        unsigned qv = 0, kv = 0, vv = 0;
        if (n < NN) {
            size_t base = (size_t)(w * NN + n);
            qv = g_qw [base * 128 + head * 16 + d2];
            kv = g_kvw[base * 256 + head * 16 + d2];
            vv = g_kvw[base * 256 + 128 + head * 16 + d2];
        }
        *(unsigned*)&qs[n][2 * d2] = qv;
        *(unsigned*)&ks[n][2 * d2] = kv;
        *(unsigned*)&vs[n][2 * d2] = vv;
    }
    __syncthreads();

    for (int mt = warp; mt < 7; mt += 4) {
        const int m0 = mt * 16;
        // Q A-frags: 2 k-tiles (dims 0-15, 16-31)
        unsigned aq[2][4];
        {
            const bf16* p0 = &qs[m0 + (lane & 15)][(lane >> 4) << 3];
            ldm_x4(aq[0][0], aq[0][1], aq[0][2], aq[0][3], p0);
            ldm_x4(aq[1][0], aq[1][1], aq[1][2], aq[1][3], p0 + 16);
        }

        float sacc[14][4];
        #pragma unroll
        for (int j = 0; j < 14; j++)
            #pragma unroll
            for (int r = 0; r < 4; r++) sacc[j][r] = 0.f;

        // S = Q @ K^T over 7 n-tile pairs
        #pragma unroll
        for (int np = 0; np < 7; np++) {
            const int n0 = np * 16;
            const bf16* kp = &ks[n0 + (lane & 7) + ((lane >> 4) << 3)][((lane >> 3) & 1) << 3];
            unsigned b0[4], b1[4];
            ldm_x4(b0[0], b0[1], b0[2], b0[3], kp);         // dims 0-15
            ldm_x4(b1[0], b1[1], b1[2], b1[3], kp + 16);    // dims 16-31
            mma_bf16(sacc[2*np],     aq[0][0], aq[0][1], aq[0][2], aq[0][3], b0[0], b0[1]);
            mma_bf16(sacc[2*np + 1], aq[0][0], aq[0][1], aq[0][2], aq[0][3], b0[2], b0[3]);
            mma_bf16(sacc[2*np],     aq[1][0], aq[1][1], aq[1][2], aq[1][3], b1[0], b1[1]);
            mma_bf16(sacc[2*np + 1], aq[1][0], aq[1][1], aq[1][2], aq[1][3], b1[2], b1[3]);
        }

        // bias + exp + rowsum  (rows r0 = m0+gid, r1 = r0+8)
        const int r0 = m0 + gid, r1 = r0 + 8;
        const int cn0 = (r0 < NN) ? (9 * ((r0 * 205) >> 11) + r0 + 180) : 180;
        const int cn1 = (r1 < NN) ? (9 * ((r1 * 205) >> 11) + r1 + 180) : 180;
        float l0 = 0.f, l1 = 0.f;
        #pragma unroll
        for (int j = 0; j < 14; j++) {
            int cA = 8 * j + 2 * tig, cB = cA + 1;
            if (cA < NN) {
                int dmA = 9 * ((cA * 205) >> 11) + cA;
                float bA = rs[cn0 - dmA], bA1 = rs[cn1 - dmA];
                float p0 = __expf(sacc[j][0] + bA);
                float p2 = __expf(sacc[j][2] + bA1);
                sacc[j][0] = p0; sacc[j][2] = p2; l0 += p0; l1 += p2;
            } else { sacc[j][0] = 0.f; sacc[j][2] = 0.f; }
            if (cB < NN) {
                int dmB = 9 * ((cB * 205) >> 11) + cB;
                float bB = rs[cn0 - dmB], bB1 = rs[cn1 - dmB];
                float p1 = __expf(sacc[j][1] + bB);
                float p3 = __expf(sacc[j][3] + bB1);
                sacc[j][1] = p1; sacc[j][3] = p3; l0 += p1; l1 += p3;
            } else { sacc[j][1] = 0.f; sacc[j][3] = 0.f; }
        }
        l0 += __shfl_xor_sync(0xffffffffu, l0, 1);
        l0 += __shfl_xor_sync(0xffffffffu, l0, 2);
        l1 += __shfl_xor_sync(0xffffffffu, l1, 1);
        l1 += __shfl_xor_sync(0xffffffffu, l1, 2);

        // PV: out[16][32]
        float oacc[4][4];
        #pragma unroll
        for (int j = 0; j < 4; j++)
            #pragma unroll
            for (int r = 0; r < 4; r++) oacc[j][r] = 0.f;

        #pragma unroll
        for (int kt = 0; kt < 7; kt++) {
            unsigned pa0 = packbf(sacc[2*kt][0],     sacc[2*kt][1]);
            unsigned pa1 = packbf(sacc[2*kt][2],     sacc[2*kt][3]);
            unsigned pa2 = packbf(sacc[2*kt + 1][0], sacc[2*kt + 1][1]);
            unsigned pa3 = packbf(sacc[2*kt + 1][2], sacc[2*kt + 1][3]);
            const bf16* vp = &vs[kt * 16 + (lane & 7) + (((lane >> 3) & 1) << 3)][(lane >> 4) << 3];
            unsigned v0[4], v1[4];
            ldm_x4t(v0[0], v0[1], v0[2], v0[3], vp);        // dims 0-15
            ldm_x4t(v1[0], v1[1], v1[2], v1[3], vp + 16);   // dims 16-31
            mma_bf16(oacc[0], pa0, pa1, pa2, pa3, v0[0], v0[1]);
            mma_bf16(oacc[1], pa0, pa1, pa2, pa3, v0[2], v0[3]);
            mma_bf16(oacc[2], pa0, pa1, pa2, pa3, v1[0], v1[1]);
            mma_bf16(oacc[3], pa0, pa1, pa2, pa3, v1[2], v1[3]);
        }

        float inv0 = 1.0f / l0, inv1 = 1.0f / l1;
        if (r0 < NN) {
            unsigned* op = &g_ow[((size_t)(w * NN + r0)) * 128 + head * 16];
            #pragma unroll
            for (int j = 0; j < 4; j++)
                op[4 * j + tig] = packbf(oacc[j][0] * inv0, oacc[j][1] * inv0);
        }
        if (r1 < NN) {
            unsigned* op = &g_ow[((size_t)(w * NN + r1)) * 128 + head * 16];
            #pragma unroll
            for (int j = 0; j < 4; j++)
                op[4 * j + tig] = packbf(oacc[j][2] * inv1, oacc[j][3] * inv1);
        }
    }
}

// ---------------- Depthwise 3x3 conv: channel-pair threads, h-loop reg ring ----------
__global__ __launch_bounds__(128)
void dwconv_kernel(const float* __restrict__ dw_w, const float* __restrict__ dw_b) {
    int c2 = blockIdx.x * 128 + threadIdx.x;   // 0..511
    int w  = blockIdx.y;
    int ca = 2 * c2, cb = 2 * c2 + 1;
    float wka[9], wkb[9];
    #pragma unroll
    for (int t = 0; t < 9; t++) { wka[t] = dw_w[ca * 9 + t]; wkb[t] = dw_w[cb * 9 + t]; }
    float ba = dw_b[ca], bb = dw_b[cb];
    bool vL = (w > 0), vR = (w < WW - 1);

    float2 row[3][3];
    #pragma unroll
    for (int a = 0; a < 3; a++)
        #pragma unroll
        for (int bz = 0; bz < 3; bz++) row[a][bz] = make_float2(0.f, 0.f);

    auto LD = [&](int hh, int wp, bool v) -> float2 {
        if (!v) return make_float2(0.f, 0.f);
        return unpackbf(g_fw[((size_t)hh * WW + wp) * 512 + c2]);
    };
    row[1][0] = LD(0, w - 1, vL); row[1][1] = LD(0, w, true); row[1][2] = LD(0, w + 1, vR);
    row[2][0] = LD(1, w - 1, vL); row[2][1] = LD(1, w, true); row[2][2] = LD(1, w + 1, vR);

    for (int h = 0; h < HH; h++) {
        float oa = ba, ob = bb;
        #pragma unroll
        for (int ri = 0; ri < 3; ri++)
            #pragma unroll
            for (int wi = 0; wi < 3; wi++) {
                oa = fmaf(row[ri][wi].x, wka[ri * 3 + wi], oa);
                ob = fmaf(row[ri][wi].y, wkb[ri * 3 + wi], ob);
            }
        g_f2w[((size_t)h * WW + w) * 512 + c2] = packbf(gelu_exact(oa), gelu_exact(ob));
        #pragma unroll
        for (int wi = 0; wi < 3; wi++) { row[0][wi] = row[1][wi]; row[1][wi] = row[2][wi]; }
        bool vH = (h + 2 < HH);
        row[2][0] = LD(h + 2, w - 1, vL && vH);
        row[2][1] = LD(h + 2, w,     vH);
        row[2][2] = LD(h + 2, w + 1, vR && vH);
    }
}

// ---------------- launch ----------------
extern "C" void kernel_launch(void* const* d_in, const int* in_sizes, int n_in,
                              void* d_out, int out_size) {
    const float* x       = (const float*)d_in[0];
    const float* norm1_g = (const float*)d_in[1];
    const float* norm1_b = (const float*)d_in[2];
    const float* wq      = (const float*)d_in[3];
    const float* bq      = (const float*)d_in[4];
    const float* wkv     = (const float*)d_in[5];
    const float* bkv     = (const float*)d_in[6];
    const float* rpb     = (const float*)d_in[7];
    const float* proj_w  = (const float*)d_in[8];
    const float* proj_b  = (const float*)d_in[9];
    const float* norm2_g = (const float*)d_in[10];
    const float* norm2_b = (const float*)d_in[11];
    const float* l1_w    = (const float*)d_in[12];
    const float* l1_b    = (const float*)d_in[13];
    const float* dw_w    = (const float*)d_in[14];
    const float* dw_b    = (const float*)d_in[15];
    const float* l2_w    = (const float*)d_in[16];
    const float* l2_b    = (const float*)d_in[17];
    float* out = (float*)d_out;

    unsigned *pqkv, *pproj, *pl1, *pl2;
    cudaGetSymbolAddress((void**)&pqkv,  p_qkv);
    cudaGetSymbolAddress((void**)&pproj, p_proj);
    cudaGetSymbolAddress((void**)&pl1,   p_l1);
    cudaGetSymbolAddress((void**)&pl2,   p_l2);

    pack_all<<<1536, 256>>>(wq, wkv, proj_w, l1_w, l2_w);
    ln_kernel<0><<<NTOK / 8, 256>>>(x, norm1_g, norm1_b);
    tgemm<0><<<dim3(6, MROWS / 128), 256>>>(pqkv,  bq,     bkv,     nullptr, nullptr, 768, DIM);
    attn_mma<<<NWIN * NH, 128>>>(rpb);
    tgemm<2><<<dim3(2, MROWS / 128), 256>>>(pproj, proj_b, nullptr, x,       nullptr, DIM, DIM);
    ln_kernel<1><<<NTOK / 8, 256>>>(nullptr, norm2_g, norm2_b);
    tgemm<3><<<dim3(8, MROWS / 128), 256>>>(pl1,   l1_b,   nullptr, nullptr, nullptr, HID, DIM);
    dwconv_kernel<<<dim3(4, WW), 128>>>(dw_w, dw_b);
    tgemm<4><<<dim3(2, MROWS / 128), 256>>>(pl2,   l2_b,   nullptr, nullptr, out,     DIM, HID);
}

// round 8
// speedup vs baseline: 4.9674x; 1.0110x over previous
#include <cuda_runtime.h>
#include <cuda_bf16.h>
#include <math.h>
#include <stdint.h>

// ---------------- problem constants ----------------
#define HH    320
#define WW    320
#define DIM   256
#define WIN   10
#define NH    8
#define HD    32
#define NTOK  (HH*WW)            // 102400
#define NWIN  (32*32)            // 1024
#define NN    (WIN*WIN)          // 100
#define MROWS NTOK
#define HID   1024
#define SCALE 0.17677669529663687f
#define LNEPS 1e-5f

typedef __nv_bfloat16 bf16;

// ---------------- scratch (words = bf16x2 unless noted) ----------------
__device__ unsigned g_winw[MROWS*128];   // LN1 out, window order
__device__ unsigned g_qw  [MROWS*128];   // Q (scaled)
__device__ unsigned g_kvw [MROWS*256];   // K | V
__device__ unsigned g_ow  [MROWS*128];   // attention out, window order
__device__ float    g_x2  [MROWS*256];   // x + attn branch (fp32, token order)
__device__ unsigned g_h2w [MROWS*128];   // LN2 out
__device__ unsigned g_fw  [MROWS*512];   // gelu(h2@l1+b), NHWC
__device__ unsigned g_f2w [MROWS*512];   // gelu(dwconv+b)

// plain bf16 weights, [K][N] row-major
__device__ bf16 p_qkvB[256*768];
__device__ bf16 p_projB[256*256];
__device__ bf16 p_l1B [256*1024];
__device__ bf16 p_l2B [1024*256];

__device__ __forceinline__ float gelu_exact(float v) {
    return 0.5f * v * (1.0f + erff(v * 0.70710678118654752f));
}
__device__ __forceinline__ unsigned packbf(float a, float b) {
    __nv_bfloat162 t = __floats2bfloat162_rn(a, b);
    return *(unsigned*)&t;
}
__device__ __forceinline__ float2 unpackbf(unsigned u) {
    return __bfloat1622float2(*(__nv_bfloat162*)&u);
}
__device__ __forceinline__ void mma_bf16(float c[4], unsigned a0, unsigned a1,
                                         unsigned a2, unsigned a3,
                                         unsigned b0, unsigned b1) {
    asm volatile("mma.sync.aligned.m16n8k16.row.col.f32.bf16.bf16.f32 "
                 "{%0,%1,%2,%3}, {%4,%5,%6,%7}, {%8,%9}, {%0,%1,%2,%3};"
                 : "+f"(c[0]), "+f"(c[1]), "+f"(c[2]), "+f"(c[3])
                 : "r"(a0), "r"(a1), "r"(a2), "r"(a3), "r"(b0), "r"(b1));
}
__device__ __forceinline__ void cp16(void* smem, const void* g) {
    unsigned s = (unsigned)__cvta_generic_to_shared(smem);
    asm volatile("cp.async.cg.shared.global [%0], [%1], 16;" :: "r"(s), "l"(g));
}
__device__ __forceinline__ void ldm_x4(unsigned& r0, unsigned& r1, unsigned& r2,
                                       unsigned& r3, const void* p) {
    unsigned s = (unsigned)__cvta_generic_to_shared(p);
    asm volatile("ldmatrix.sync.aligned.m8n8.x4.shared.b16 {%0,%1,%2,%3}, [%4];"
                 : "=r"(r0), "=r"(r1), "=r"(r2), "=r"(r3) : "r"(s));
}
__device__ __forceinline__ void ldm_x4t(unsigned& r0, unsigned& r1, unsigned& r2,
                                        unsigned& r3, const void* p) {
    unsigned s = (unsigned)__cvta_generic_to_shared(p);
    asm volatile("ldmatrix.sync.aligned.m8n8.x4.trans.shared.b16 {%0,%1,%2,%3}, [%4];"
                 : "=r"(r0), "=r"(r1), "=r"(r2), "=r"(r3) : "r"(s));
}

// ---------------- weight pack: f32 -> plain bf16 [K][N] ----------------
__global__ void pack_all(const float* __restrict__ wq, const float* __restrict__ wkv,
                         const float* __restrict__ proj_w, const float* __restrict__ l1_w,
                         const float* __restrict__ l2_w) {
    int i = blockIdx.x * 256 + threadIdx.x;
    if (i < 196608) {                     // qkvB [256][768]
        int k = i / 768, n = i - k * 768;
        float v = (n < 256) ? wq[k * 256 + n] : wkv[k * 512 + (n - 256)];
        p_qkvB[i] = __float2bfloat16(v);
    } else if (i < 262144) {              // projB [256][256]
        int j = i - 196608;
        p_projB[j] = __float2bfloat16(proj_w[j]);
    } else if (i < 524288) {              // l1B [256][1024]
        int j = i - 262144;
        p_l1B[j] = __float2bfloat16(l1_w[j]);
    } else if (i < 786432) {              // l2B [1024][256]
        int j = i - 524288;
        p_l2B[j] = __float2bfloat16(l2_w[j]);
    }
}

// ---------------- LayerNorm: warp per token ----------------
template<int M>   // M=0: x -> g_winw (window perm); M=1: g_x2 -> g_h2w
__global__ __launch_bounds__(256)
void ln_kernel(const float* __restrict__ xin,
               const float* __restrict__ g, const float* __restrict__ b) {
    int warp = threadIdx.x >> 5, lane = threadIdx.x & 31;
    int t = blockIdx.x * 8 + warp;
    const float* src = (M == 0) ? xin : g_x2;
    const float4* xp = (const float4*)(src + (size_t)t * DIM) + lane * 2;
    float4 f0 = xp[0], f1 = xp[1];
    float s  = f0.x + f0.y + f0.z + f0.w + f1.x + f1.y + f1.z + f1.w;
    float ss = f0.x*f0.x + f0.y*f0.y + f0.z*f0.z + f0.w*f0.w
             + f1.x*f1.x + f1.y*f1.y + f1.z*f1.z + f1.w*f1.w;
    #pragma unroll
    for (int o = 16; o; o >>= 1) {
        s  += __shfl_xor_sync(0xffffffffu, s,  o);
        ss += __shfl_xor_sync(0xffffffffu, ss, o);
    }
    float mean = s * (1.0f / DIM);
    float rstd = rsqrtf(ss * (1.0f / DIM) - mean * mean + LNEPS);
    const float4* gp = (const float4*)g + lane * 2;
    const float4* bp = (const float4*)b + lane * 2;
    float4 g0 = gp[0], g1 = gp[1], b0 = bp[0], b1 = bp[1];
    unsigned w0 = packbf((f0.x-mean)*rstd*g0.x + b0.x, (f0.y-mean)*rstd*g0.y + b0.y);
    unsigned w1 = packbf((f0.z-mean)*rstd*g0.z + b0.z, (f0.w-mean)*rstd*g0.w + b0.w);
    unsigned w2 = packbf((f1.x-mean)*rstd*g1.x + b1.x, (f1.y-mean)*rstd*g1.y + b1.y);
    unsigned w3 = packbf((f1.z-mean)*rstd*g1.z + b1.z, (f1.w-mean)*rstd*g1.w + b1.w);
    size_t r;
    if constexpr (M == 0) {
        int h = t / WW, w = t - h * WW;
        r = ((h / WIN) * 32 + (w / WIN)) * NN + (h % WIN) * WIN + (w % WIN);
    } else r = t;
    unsigned* dst = (M == 0) ? g_winw : g_h2w;
    *(uint4*)&dst[r * 128 + lane * 4] = make_uint4(w0, w1, w2, w3);
}

// ---------------- bf16 MMA GEMM, 4-stage cp.async, ldmatrix A + B ----------------
// 128x128x32 tile, 256 threads, warp 2(M)x4(N), warp tile 64x32.
// A smem: 16 words/row (32 halves), chunk swizzle ^((row>>1)&3).
// B smem: plain [k 32][n 128 halves] = 64 words/row, word swizzle ^((k&7)<<3).
// MODE 0: g_winw @ qkvB (N=768): c<256 -> q (scaled) else kv
// MODE 2: g_ow @ projB -> g_x2 (window reverse + residual x)
// MODE 3: g_h2w @ l1B -> g_fw (gelu)
// MODE 4: g_f2w @ l2B -> out (+ g_x2)
#define TG_SMEM 65536

template<int MODE>
__launch_bounds__(256)
__global__ void tgemm(const bf16* __restrict__ Bw, const float* __restrict__ bias,
                      const float* __restrict__ bias2, const float* __restrict__ res,
                      float* __restrict__ Coutf, int Ndim, int Kdim) {
    const bf16* A;
    if constexpr (MODE == 0) A = (const bf16*)g_winw;
    else if constexpr (MODE == 2) A = (const bf16*)g_ow;
    else if constexpr (MODE == 3) A = (const bf16*)g_h2w;
    else A = (const bf16*)g_f2w;

    extern __shared__ unsigned smem[];
    unsigned* Asm = smem;            // 4 stages x 2048 words
    unsigned* Bsm = smem + 8192;     // 4 stages x 2048 words

    const int tid  = threadIdx.x;
    const int bx   = blockIdx.x, by = blockIdx.y;
    const int lane = tid & 31;
    const int warp = tid >> 5;
    const int warpM = warp & 1;
    const int warpN = warp >> 1;
    const int gid = lane >> 2;
    const int tig = lane & 3;

    const int tiles = Kdim / 32;

    float acc[4][4][4];
    #pragma unroll
    for (int i = 0; i < 4; i++)
        #pragma unroll
        for (int j = 0; j < 4; j++)
            #pragma unroll
            for (int r = 0; r < 4; r++) acc[i][j][r] = 0.f;

    // loader mapping
    const int arow = tid >> 2, ac = tid & 3;
    const int aoff = arow * 16 + ((ac ^ ((arow >> 1) & 3)) << 2);
    const int brow = tid >> 4, bseg = tid & 15;        // B: 2 chunks per thread (rows brow, brow+16)
    const int boff0 = brow * 64        + (((bseg << 2)) ^ ((brow & 7) << 3));
    const int boff1 = (brow + 16) * 64 + (((bseg << 2)) ^ (((brow + 16) & 7) << 3));
    const bf16* Abase = A  + (size_t)(by * 128) * Kdim;
    const bf16* Bbase = Bw + (size_t)bx * 128;

#define LOAD_STAGE(T, ST)                                                                         \
    {                                                                                             \
        unsigned* Asr = Asm + (ST) * 2048;                                                        \
        unsigned* Bsr = Bsm + (ST) * 2048;                                                        \
        cp16(Asr + aoff,            Abase + (size_t)(arow)      * Kdim + (T) * 32 + ac * 8);      \
        cp16(Asr + aoff + 64 * 16,  Abase + (size_t)(arow + 64) * Kdim + (T) * 32 + ac * 8);      \
        cp16(Bsr + boff0, Bbase + (size_t)((T) * 32 + brow)      * Ndim + bseg * 8);              \
        cp16(Bsr + boff1, Bbase + (size_t)((T) * 32 + brow + 16) * Ndim + bseg * 8);              \
        asm volatile("cp.async.commit_group;");                                                   \
    }

    LOAD_STAGE(0, 0);
    if (tiles > 1) LOAD_STAGE(1, 1);
    if (tiles > 2) LOAD_STAGE(2, 2);

    // fragment addressing constants
    const int rbase = warpM * 64 + (lane & 15);
    const int km    = (rbase >> 1) & 3;
    const int cbit  = lane >> 4;
    const int krlo  = (lane & 7) + ((lane >> 3) & 1) * 8;   // 0..15 within k16
    const int bw    = warpN * 16 + (lane >> 4) * 4;         // word base (first n16 group)

    for (int t = 0; t < tiles; t++) {
        if (t + 2 < tiles)      asm volatile("cp.async.wait_group 2;");
        else if (t + 1 < tiles) asm volatile("cp.async.wait_group 1;");
        else                    asm volatile("cp.async.wait_group 0;");
        __syncthreads();
        if (t + 3 < tiles) LOAD_STAGE(t + 3, (t + 3) & 3);

        const unsigned* Ast = Asm + (t & 3) * 2048;
        const unsigned* Bst = Bsm + (t & 3) * 2048;
        #pragma unroll
        for (int s = 0; s < 2; s++) {
            const int aswz = ((s * 2 + cbit) ^ km) << 2;
            unsigned af[4][4];
            #pragma unroll
            for (int i = 0; i < 4; i++)
                ldm_x4(af[i][0], af[i][1], af[i][2], af[i][3],
                       Ast + (rbase + i * 16) * 16 + aswz);
            const int kr = s * 16 + krlo;
            unsigned t0[4], t1[4];
            ldm_x4t(t0[0], t0[1], t0[2], t0[3],
                    Bst + kr * 64 + ((bw)     ^ ((kr & 7) << 3)));
            ldm_x4t(t1[0], t1[1], t1[2], t1[3],
                    Bst + kr * 64 + ((bw + 8) ^ ((kr & 7) << 3)));
            #pragma unroll
            for (int i = 0; i < 4; i++) {
                mma_bf16(acc[i][0], af[i][0], af[i][1], af[i][2], af[i][3], t0[0], t0[1]);
                mma_bf16(acc[i][1], af[i][0], af[i][1], af[i][2], af[i][3], t0[2], t0[3]);
                mma_bf16(acc[i][2], af[i][0], af[i][1], af[i][2], af[i][3], t1[0], t1[1]);
                mma_bf16(acc[i][3], af[i][0], af[i][1], af[i][2], af[i][3], t1[2], t1[3]);
            }
        }
        __syncthreads();
    }
#undef LOAD_STAGE

    // ---------------- epilogue ----------------
    const int rowBase = by * 128 + warpM * 64;
    const int colBase = bx * 128 + warpN * 32;
    #pragma unroll
    for (int i = 0; i < 4; i++) {
        #pragma unroll
        for (int j = 0; j < 4; j++) {
            #pragma unroll
            for (int half = 0; half < 2; half++) {
                int r = rowBase + i * 16 + gid + half * 8;
                int c = colBase + j * 8 + tig * 2;
                float a0 = acc[i][j][half * 2 + 0];
                float a1 = acc[i][j][half * 2 + 1];
                if constexpr (MODE == 0) {
                    if (c < 256) {
                        g_qw[(size_t)r * 128 + (c >> 1)] =
                            packbf((a0 + bias[c]) * SCALE, (a1 + bias[c + 1]) * SCALE);
                    } else {
                        int cc = c - 256;
                        g_kvw[(size_t)r * 256 + (cc >> 1)] =
                            packbf(a0 + bias2[cc], a1 + bias2[cc + 1]);
                    }
                } else if constexpr (MODE == 2) {
                    float v0 = a0 + bias[c], v1 = a1 + bias[c + 1];
                    int wwin = r / NN, p = r - wwin * NN;
                    int tok = ((wwin >> 5) * WIN + p / WIN) * WW + (wwin & 31) * WIN + (p % WIN);
                    g_x2[(size_t)tok * DIM + c]     = res[(size_t)tok * DIM + c]     + v0;
                    g_x2[(size_t)tok * DIM + c + 1] = res[(size_t)tok * DIM + c + 1] + v1;
                } else if constexpr (MODE == 3) {
                    g_fw[(size_t)r * 512 + (c >> 1)] =
                        packbf(gelu_exact(a0 + bias[c]), gelu_exact(a1 + bias[c + 1]));
                } else {
                    Coutf[(size_t)r * Ndim + c]     = g_x2[(size_t)r * DIM + c]     + a0 + bias[c];
                    Coutf[(size_t)r * Ndim + c + 1] = g_x2[(size_t)r * DIM + c + 1] + a1 + bias[c + 1];
                }
            }
        }
    }
}

// ---------------- Windowed attention via tensor cores (256 thr, 1 mt/warp) ----------
__global__ __launch_bounds__(256)
void attn_mma(const float* __restrict__ rpb) {
    __shared__ bf16 qs[112][40];
    __shared__ bf16 ks[112][40];
    __shared__ bf16 vs[112][40];
    __shared__ float rs[361];

    const int blk  = blockIdx.x;
    const int w    = blk >> 3;
    const int head = blk & 7;
    const int tid  = threadIdx.x;
    const int warp = tid >> 5;
    const int lane = tid & 31;
    const int gid  = lane >> 2;
    const int tig  = lane & 3;

    for (int i = tid; i < 361; i += 256) rs[i] = rpb[i * NH + head];
    // 112 rows x 4 uint4 chunks per array (pad rows zero)
    for (int i = tid; i < 448; i += 256) {
        int n = i >> 2, q = i & 3;
        uint4 qv = make_uint4(0, 0, 0, 0), kv = qv, vv = qv;
        if (n < NN) {
            size_t base = (size_t)(w * NN + n);
            qv = *(const uint4*)&g_qw [base * 128 + head * 16 + q * 4];
            kv = *(const uint4*)&g_kvw[base * 256 + head * 16 + q * 4];
            vv = *(const uint4*)&g_kvw[base * 256 + 128 + head * 16 + q * 4];
        }
        *(uint4*)&qs[n][q * 8] = qv;
        *(uint4*)&ks[n][q * 8] = kv;
        *(uint4*)&vs[n][q * 8] = vv;
    }
    __syncthreads();

    if (warp < 7) {
        const int m0 = warp * 16;
        unsigned aq[2][4];
        {
            const bf16* p0 = &qs[m0 + (lane & 15)][(lane >> 4) << 3];
            ldm_x4(aq[0][0], aq[0][1], aq[0][2], aq[0][3], p0);
            ldm_x4(aq[1][0], aq[1][1], aq[1][2], aq[1][3], p0 + 16);
        }

        float sacc[14][4];
        #pragma unroll
        for (int j = 0; j < 14; j++)
            #pragma unroll
            for (int r = 0; r < 4; r++) sacc[j][r] = 0.f;

        #pragma unroll
        for (int np = 0; np < 7; np++) {
            const int n0 = np * 16;
            const bf16* kp = &ks[n0 + (lane & 7) + ((lane >> 4) << 3)][((lane >> 3) & 1) << 3];
            unsigned b0[4], b1[4];
            ldm_x4(b0[0], b0[1], b0[2], b0[3], kp);
            ldm_x4(b1[0], b1[1], b1[2], b1[3], kp + 16);
            mma_bf16(sacc[2*np],     aq[0][0], aq[0][1], aq[0][2], aq[0][3], b0[0], b0[1]);
            mma_bf16(sacc[2*np + 1], aq[0][0], aq[0][1], aq[0][2], aq[0][3], b0[2], b0[3]);
            mma_bf16(sacc[2*np],     aq[1][0], aq[1][1], aq[1][2], aq[1][3], b1[0], b1[1]);
            mma_bf16(sacc[2*np + 1], aq[1][0], aq[1][1], aq[1][2], aq[1][3], b1[2], b1[3]);
        }

        const int r0 = m0 + gid, r1 = r0 + 8;
        const int cn0 = (r0 < NN) ? (9 * ((r0 * 205) >> 11) + r0 + 180) : 180;
        const int cn1 = (r1 < NN) ? (9 * ((r1 * 205) >> 11) + r1 + 180) : 180;
        float l0 = 0.f, l1 = 0.f;
        #pragma unroll
        for (int j = 0; j < 14; j++) {
            int cA = 8 * j + 2 * tig, cB = cA + 1;
            if (cA < NN) {
                int dmA = 9 * ((cA * 205) >> 11) + cA;
                float bA = rs[cn0 - dmA], bA1 = rs[cn1 - dmA];
                float p0 = __expf(sacc[j][0] + bA);
                float p2 = __expf(sacc[j][2] + bA1);
                sacc[j][0] = p0; sacc[j][2] = p2; l0 += p0; l1 += p2;
            } else { sacc[j][0] = 0.f; sacc[j][2] = 0.f; }
            if (cB < NN) {
                int dmB = 9 * ((cB * 205) >> 11) + cB;
                float bB = rs[cn0 - dmB], bB1 = rs[cn1 - dmB];
                float p1 = __expf(sacc[j][1] + bB);
                float p3 = __expf(sacc[j][3] + bB1);
                sacc[j][1] = p1; sacc[j][3] = p3; l0 += p1; l1 += p3;
            } else { sacc[j][1] = 0.f; sacc[j][3] = 0.f; }
        }
        l0 += __shfl_xor_sync(0xffffffffu, l0, 1);
        l0 += __shfl_xor_sync(0xffffffffu, l0, 2);
        l1 += __shfl_xor_sync(0xffffffffu, l1, 1);
        l1 += __shfl_xor_sync(0xffffffffu, l1, 2);

        float oacc[4][4];
        #pragma unroll
        for (int j = 0; j < 4; j++)
            #pragma unroll
            for (int r = 0; r < 4; r++) oacc[j][r] = 0.f;

        #pragma unroll
        for (int kt = 0; kt < 7; kt++) {
            unsigned pa0 = packbf(sacc[2*kt][0],     sacc[2*kt][1]);
            unsigned pa1 = packbf(sacc[2*kt][2],     sacc[2*kt][3]);
            unsigned pa2 = packbf(sacc[2*kt + 1][0], sacc[2*kt + 1][1]);
            unsigned pa3 = packbf(sacc[2*kt + 1][2], sacc[2*kt + 1][3]);
            const bf16* vp = &vs[kt * 16 + (lane & 7) + (((lane >> 3) & 1) << 3)][(lane >> 4) << 3];
            unsigned v0[4], v1[4];
            ldm_x4t(v0[0], v0[1], v0[2], v0[3], vp);
            ldm_x4t(v1[0], v1[1], v1[2], v1[3], vp + 16);
            mma_bf16(oacc[0], pa0, pa1, pa2, pa3, v0[0], v0[1]);
            mma_bf16(oacc[1], pa0, pa1, pa2, pa3, v0[2], v0[3]);
            mma_bf16(oacc[2], pa0, pa1, pa2, pa3, v1[0], v1[1]);
            mma_bf16(oacc[3], pa0, pa1, pa2, pa3, v1[2], v1[3]);
        }

        float inv0 = 1.0f / l0, inv1 = 1.0f / l1;
        if (r0 < NN) {
            unsigned* op = &g_ow[((size_t)(w * NN + r0)) * 128 + head * 16];
            #pragma unroll
            for (int j = 0; j < 4; j++)
                op[4 * j + tig] = packbf(oacc[j][0] * inv0, oacc[j][1] * inv0);
        }
        if (r1 < NN) {
            unsigned* op = &g_ow[((size_t)(w * NN + r1)) * 128 + head * 16];
            #pragma unroll
            for (int j = 0; j < 4; j++)
                op[4 * j + tig] = packbf(oacc[j][2] * inv1, oacc[j][3] * inv1);
        }
    }
}

// ---------------- Depthwise 3x3 conv: channel-pair threads, h-loop reg ring ----------
__global__ __launch_bounds__(128)
void dwconv_kernel(const float* __restrict__ dw_w, const float* __restrict__ dw_b) {
    int c2 = blockIdx.x * 128 + threadIdx.x;
    int w  = blockIdx.y;
    int ca = 2 * c2, cb = 2 * c2 + 1;
    float wka[9], wkb[9];
    #pragma unroll
    for (int t = 0; t < 9; t++) { wka[t] = dw_w[ca * 9 + t]; wkb[t] = dw_w[cb * 9 + t]; }
    float ba = dw_b[ca], bb = dw_b[cb];
    bool vL = (w > 0), vR = (w < WW - 1);

    float2 row[3][3];
    #pragma unroll
    for (int a = 0; a < 3; a++)
        #pragma unroll
        for (int bz = 0; bz < 3; bz++) row[a][bz] = make_float2(0.f, 0.f);

    auto LD = [&](int hh, int wp, bool v) -> float2 {
        if (!v) return make_float2(0.f, 0.f);
        return unpackbf(g_fw[((size_t)hh * WW + wp) * 512 + c2]);
    };
    row[1][0] = LD(0, w - 1, vL); row[1][1] = LD(0, w, true); row[1][2] = LD(0, w + 1, vR);
    row[2][0] = LD(1, w - 1, vL); row[2][1] = LD(1, w, true); row[2][2] = LD(1, w + 1, vR);

    for (int h = 0; h < HH; h++) {
        float oa = ba, ob = bb;
        #pragma unroll
        for (int ri = 0; ri < 3; ri++)
            #pragma unroll
            for (int wi = 0; wi < 3; wi++) {
                oa = fmaf(row[ri][wi].x, wka[ri * 3 + wi], oa);
                ob = fmaf(row[ri][wi].y, wkb[ri * 3 + wi], ob);
            }
        g_f2w[((size_t)h * WW + w) * 512 + c2] = packbf(gelu_exact(oa), gelu_exact(ob));
        #pragma unroll
        for (int wi = 0; wi < 3; wi++) { row[0][wi] = row[1][wi]; row[1][wi] = row[2][wi]; }
        bool vH = (h + 2 < HH);
        row[2][0] = LD(h + 2, w - 1, vL && vH);
        row[2][1] = LD(h + 2, w,     vH);
        row[2][2] = LD(h + 2, w + 1, vR && vH);
    }
}

// ---------------- launch ----------------
extern "C" void kernel_launch(void* const* d_in, const int* in_sizes, int n_in,
                              void* d_out, int out_size) {
    const float* x       = (const float*)d_in[0];
    const float* norm1_g = (const float*)d_in[1];
    const float* norm1_b = (const float*)d_in[2];
    const float* wq      = (const float*)d_in[3];
    const float* bq      = (const float*)d_in[4];
    const float* wkv     = (const float*)d_in[5];
    const float* bkv     = (const float*)d_in[6];
    const float* rpb     = (const float*)d_in[7];
    const float* proj_w  = (const float*)d_in[8];
    const float* proj_b  = (const float*)d_in[9];
    const float* norm2_g = (const float*)d_in[10];
    const float* norm2_b = (const float*)d_in[11];
    const float* l1_w    = (const float*)d_in[12];
    const float* l1_b    = (const float*)d_in[13];
    const float* dw_w    = (const float*)d_in[14];
    const float* dw_b    = (const float*)d_in[15];
    const float* l2_w    = (const float*)d_in[16];
    const float* l2_b    = (const float*)d_in[17];
    float* out = (float*)d_out;

    bf16 *pqkv, *pproj, *pl1, *pl2;
    cudaGetSymbolAddress((void**)&pqkv,  p_qkvB);
    cudaGetSymbolAddress((void**)&pproj, p_projB);
    cudaGetSymbolAddress((void**)&pl1,   p_l1B);
    cudaGetSymbolAddress((void**)&pl2,   p_l2B);

    cudaFuncSetAttribute(tgemm<0>, cudaFuncAttributeMaxDynamicSharedMemorySize, TG_SMEM);
    cudaFuncSetAttribute(tgemm<2>, cudaFuncAttributeMaxDynamicSharedMemorySize, TG_SMEM);
    cudaFuncSetAttribute(tgemm<3>, cudaFuncAttributeMaxDynamicSharedMemorySize, TG_SMEM);
    cudaFuncSetAttribute(tgemm<4>, cudaFuncAttributeMaxDynamicSharedMemorySize, TG_SMEM);

    pack_all<<<3072, 256>>>(wq, wkv, proj_w, l1_w, l2_w);
    ln_kernel<0><<<NTOK / 8, 256>>>(x, norm1_g, norm1_b);
    tgemm<0><<<dim3(6, MROWS / 128), 256, TG_SMEM>>>(pqkv,  bq,     bkv,     nullptr, nullptr, 768, DIM);
    attn_mma<<<NWIN * NH, 256>>>(rpb);
    tgemm<2><<<dim3(2, MROWS / 128), 256, TG_SMEM>>>(pproj, proj_b, nullptr, x,       nullptr, DIM, DIM);
    ln_kernel<1><<<NTOK / 8, 256>>>(nullptr, norm2_g, norm2_b);
    tgemm<3><<<dim3(8, MROWS / 128), 256, TG_SMEM>>>(pl1,   l1_b,   nullptr, nullptr, nullptr, HID, DIM);
    dwconv_kernel<<<dim3(4, WW), 128>>>(dw_w, dw_b);
    tgemm<4><<<dim3(2, MROWS / 128), 256, TG_SMEM>>>(pl2,   l2_b,   nullptr, nullptr, out,     DIM, HID);
}